// round 1
// baseline (speedup 1.0000x reference)
#include <cuda_runtime.h>
#include <cuda_bf16.h>
#include <cstddef>

// Problem constants
constexpr int Bv = 4;
constexpr int Tv = 2048;
constexpr int Cv = 1024;
constexpr int Hn = 16;
constexpr int Dv = 64;           // Cv / Hn
constexpr int Mv = Bv * Tv;      // 8192 rows

// Scratch (device globals; no allocation allowed)
__device__ float g_q[(size_t)Mv * Cv];   // [B*H, T, D]
__device__ float g_k[(size_t)Mv * Cv];
__device__ float g_v[(size_t)Mv * Cv];
__device__ float g_y[(size_t)Mv * Cv];   // [B, T, C] merged heads

// ---------------------------------------------------------------------------
// GEMM: out = A[M,K] @ W[N,K]^T + bias    (both K-contiguous, "NT" layout)
// Tiles: 64x64x16, 256 threads, 4x4 microtile per thread.
// split_heads==1: write out[((b*H+h)*T+t)*D+d] with m=b*T+t, n=h*D+d
// split_heads==0: write out[m*C+n]
// ---------------------------------------------------------------------------
#define GBM 64
#define GBN 64
#define GBK 16
#define GPAD 20   // row stride in floats; 20*4=80B keeps float4 alignment, avoids conflicts

__global__ __launch_bounds__(256) void gemm_nt_kernel(
    const float* __restrict__ A, const float* __restrict__ W,
    const float* __restrict__ bias, float* __restrict__ out, int split_heads)
{
    __shared__ float As[GBM][GPAD];
    __shared__ float Ws[GBN][GPAD];

    const int tid = threadIdx.x;
    const int tx = tid & 15;        // 0..15 -> N direction
    const int ty = tid >> 4;        // 0..15 -> M direction
    const int m0 = blockIdx.y * GBM;
    const int n0 = blockIdx.x * GBN;

    const int lr = tid >> 2;        // 0..63 tile row for loads
    const int lc = (tid & 3) * 4;   // 0,4,8,12 tile col (float4)

    float acc[4][4] = {};

    for (int k0 = 0; k0 < Cv; k0 += GBK) {
        float4 av = *reinterpret_cast<const float4*>(&A[(size_t)(m0 + lr) * Cv + k0 + lc]);
        float4 wv = *reinterpret_cast<const float4*>(&W[(size_t)(n0 + lr) * Cv + k0 + lc]);
        *reinterpret_cast<float4*>(&As[lr][lc]) = av;
        *reinterpret_cast<float4*>(&Ws[lr][lc]) = wv;
        __syncthreads();

        #pragma unroll
        for (int k = 0; k < GBK; k++) {
            float a[4], b[4];
            #pragma unroll
            for (int i = 0; i < 4; i++) a[i] = As[ty * 4 + i][k];
            #pragma unroll
            for (int j = 0; j < 4; j++) b[j] = Ws[tx * 4 + j][k];
            #pragma unroll
            for (int i = 0; i < 4; i++)
                #pragma unroll
                for (int j = 0; j < 4; j++)
                    acc[i][j] = fmaf(a[i], b[j], acc[i][j]);
        }
        __syncthreads();
    }

    #pragma unroll
    for (int i = 0; i < 4; i++) {
        const int m = m0 + ty * 4 + i;
        #pragma unroll
        for (int j = 0; j < 4; j++) {
            const int n = n0 + tx * 4 + j;
            const float v = acc[i][j] + bias[n];
            if (split_heads) {
                const int b = m / Tv, t = m % Tv;
                const int h = n >> 6, d = n & 63;
                out[(((size_t)(b * Hn + h)) * Tv + t) * Dv + d] = v;
            } else {
                out[(size_t)m * Cv + n] = v;
            }
        }
    }
}

// ---------------------------------------------------------------------------
// Attention: per (b,h) and 64-row Q tile, stream 64-row K/V tiles.
// S = Q K^T * scale; P = exp(S) (unnormalized, scores provably bounded);
// O += P V; final divide by row sums. 256 threads, 4x4 microtiles.
// ---------------------------------------------------------------------------
#define APAD 68   // 68*4=272B: float4-aligned rows, bank shift of 4 per row

__global__ __launch_bounds__(256) void attn_kernel(float scale)
{
    extern __shared__ float sm[];
    float* Qs = sm;                  // 64 x APAD
    float* Ks = sm + 64 * APAD;
    float* Vs = sm + 2 * 64 * APAD;
    float* Ps = sm + 3 * 64 * APAD;

    const int tid = threadIdx.x;
    const int tx = tid & 15;
    const int ty = tid >> 4;
    const int bh = blockIdx.y;           // 0..63
    const int q0 = blockIdx.x * 64;

    const float* qb = g_q + (size_t)bh * Tv * Dv;
    const float* kb = g_k + (size_t)bh * Tv * Dv;
    const float* vb = g_v + (size_t)bh * Tv * Dv;

    // load Q tile (64x64)
    #pragma unroll
    for (int i = 0; i < 4; i++) {
        const int idx = tid + i * 256;
        const int r = idx >> 4, c = (idx & 15) * 4;
        *reinterpret_cast<float4*>(&Qs[r * APAD + c]) =
            *reinterpret_cast<const float4*>(&qb[(size_t)(q0 + r) * Dv + c]);
    }

    float o[4][4] = {};
    float rs[4] = {};

    for (int s0 = 0; s0 < Tv; s0 += 64) {
        __syncthreads();   // prior PV done (and Q visible on first iter)
        #pragma unroll
        for (int i = 0; i < 4; i++) {
            const int idx = tid + i * 256;
            const int r = idx >> 4, c = (idx & 15) * 4;
            *reinterpret_cast<float4*>(&Ks[r * APAD + c]) =
                *reinterpret_cast<const float4*>(&kb[(size_t)(s0 + r) * Dv + c]);
            *reinterpret_cast<float4*>(&Vs[r * APAD + c]) =
                *reinterpret_cast<const float4*>(&vb[(size_t)(s0 + r) * Dv + c]);
        }
        __syncthreads();

        // S = Q K^T (64x64x64)
        float s[4][4] = {};
        #pragma unroll 8
        for (int kk = 0; kk < 64; kk++) {
            float a[4], b[4];
            #pragma unroll
            for (int i = 0; i < 4; i++) a[i] = Qs[(ty * 4 + i) * APAD + kk];
            #pragma unroll
            for (int j = 0; j < 4; j++) b[j] = Ks[(tx * 4 + j) * APAD + kk];
            #pragma unroll
            for (int i = 0; i < 4; i++)
                #pragma unroll
                for (int j = 0; j < 4; j++)
                    s[i][j] = fmaf(a[i], b[j], s[i][j]);
        }

        // P = exp(S*scale), stage to smem, accumulate row sums
        #pragma unroll
        for (int i = 0; i < 4; i++) {
            #pragma unroll
            for (int j = 0; j < 4; j++) {
                const float p = __expf(s[i][j] * scale);
                rs[i] += p;
                Ps[(ty * 4 + i) * APAD + tx * 4 + j] = p;
            }
        }
        __syncthreads();

        // O += P V (64x64x64, contraction over s)
        #pragma unroll 8
        for (int ss = 0; ss < 64; ss++) {
            float pv[4], b[4];
            #pragma unroll
            for (int i = 0; i < 4; i++) pv[i] = Ps[(ty * 4 + i) * APAD + ss];
            #pragma unroll
            for (int j = 0; j < 4; j++) b[j] = Vs[ss * APAD + tx * 4 + j];
            #pragma unroll
            for (int i = 0; i < 4; i++)
                #pragma unroll
                for (int j = 0; j < 4; j++)
                    o[i][j] = fmaf(pv[i], b[j], o[i][j]);
        }
    }

    // reduce row sums across the 16 lanes sharing each row group
    #pragma unroll
    for (int off = 8; off > 0; off >>= 1)
        #pragma unroll
        for (int i = 0; i < 4; i++)
            rs[i] += __shfl_xor_sync(0xffffffffu, rs[i], off, 16);

    const int b = bh / Hn, h = bh % Hn;
    #pragma unroll
    for (int i = 0; i < 4; i++) {
        const float inv = 1.0f / rs[i];
        const int t = q0 + ty * 4 + i;
        #pragma unroll
        for (int j = 0; j < 4; j++)
            g_y[((size_t)(b * Tv + t)) * Cv + h * Dv + tx * 4 + j] = o[i][j] * inv;
    }
}

// ---------------------------------------------------------------------------
extern "C" void kernel_launch(void* const* d_in, const int* in_sizes, int n_in,
                              void* d_out, int out_size)
{
    const float* x  = (const float*)d_in[0];
    const float* Wq = (const float*)d_in[1];
    const float* bq = (const float*)d_in[2];
    const float* Wk = (const float*)d_in[3];
    const float* bk = (const float*)d_in[4];
    const float* Wv = (const float*)d_in[5];
    const float* bv = (const float*)d_in[6];
    const float* Wp = (const float*)d_in[7];
    const float* bp = (const float*)d_in[8];
    float* out = (float*)d_out;

    float *qp, *kp, *vp, *yp;
    cudaGetSymbolAddress((void**)&qp, g_q);
    cudaGetSymbolAddress((void**)&kp, g_k);
    cudaGetSymbolAddress((void**)&vp, g_v);
    cudaGetSymbolAddress((void**)&yp, g_y);

    const int attn_smem = 4 * 64 * APAD * sizeof(float);   // 69632 B
    cudaFuncSetAttribute(attn_kernel, cudaFuncAttributeMaxDynamicSharedMemorySize, attn_smem);

    dim3 gGrid(Cv / GBN, Mv / GBM);   // (16, 128)
    dim3 gBlk(256);

    // QKV projections with head-split outputs
    gemm_nt_kernel<<<gGrid, gBlk>>>(x, Wq, bq, qp, 1);
    gemm_nt_kernel<<<gGrid, gBlk>>>(x, Wk, bk, kp, 1);
    gemm_nt_kernel<<<gGrid, gBlk>>>(x, Wv, bv, vp, 1);

    // attention
    dim3 aGrid(Tv / 64, Bv * Hn);     // (32, 64)
    attn_kernel<<<aGrid, gBlk, attn_smem>>>(0.125f);   // 1/sqrt(64)

    // output projection
    gemm_nt_kernel<<<gGrid, gBlk>>>(yp, Wp, bp, out, 0);
}

// round 2
// speedup vs baseline: 2.3180x; 2.3180x over previous
#include <cuda_runtime.h>
#include <cuda_bf16.h>
#include <cstddef>

// Problem constants
constexpr int Bv = 4;
constexpr int Tv = 2048;
constexpr int Cv = 1024;
constexpr int Hn = 16;
constexpr int Dv = 64;           // Cv / Hn
constexpr int Mv = Bv * Tv;      // 8192 rows

// Scratch (device globals; no allocation allowed)
__device__ float g_q[(size_t)Mv * Cv];   // [B*H, T, D]
__device__ float g_k[(size_t)Mv * Cv];
__device__ float g_v[(size_t)Mv * Cv];
__device__ float g_y[(size_t)Mv * Cv];   // [B, T, C] merged heads

// ---------------------------------------------------------------------------
// GEMM: out = A[M,K] @ W[N,K]^T + bias  (both K-contiguous, "NT")
// 128x128x16 tiles, 256 threads, 8x8 microtile, k-major smem, double buffer.
// ---------------------------------------------------------------------------
#define BM 128
#define BN 128
#define BKG 16
#define PADG 4

__global__ __launch_bounds__(256, 2) void gemm_nt_kernel(
    const float* __restrict__ A, const float* __restrict__ W,
    const float* __restrict__ bias, float* __restrict__ out, int split_heads)
{
    __shared__ float As[2][BKG][BM + PADG];
    __shared__ float Ws[2][BKG][BN + PADG];

    const int tid = threadIdx.x;
    const int tx = tid & 15;        // n dir (x8)
    const int ty = tid >> 4;        // m dir (x8)
    const int m0 = blockIdx.y * BM;
    const int n0 = blockIdx.x * BN;

    // loader: thread -> 2 float4 from A and 2 from W per k-tile
    const int lr = tid >> 2;        // 0..63
    const int lc = (tid & 3) * 4;   // 0,4,8,12

    float4 ra[2], rw[2];
    #pragma unroll
    for (int i = 0; i < 2; i++) {
        ra[i] = *reinterpret_cast<const float4*>(&A[(size_t)(m0 + lr + 64 * i) * Cv + lc]);
        rw[i] = *reinterpret_cast<const float4*>(&W[(size_t)(n0 + lr + 64 * i) * Cv + lc]);
    }
    #pragma unroll
    for (int i = 0; i < 2; i++)
        #pragma unroll
        for (int j = 0; j < 4; j++) {
            As[0][lc + j][lr + 64 * i] = reinterpret_cast<float*>(&ra[i])[j];
            Ws[0][lc + j][lr + 64 * i] = reinterpret_cast<float*>(&rw[i])[j];
        }

    float acc[8][8] = {};
    int cur = 0;

    for (int k0 = 0; k0 < Cv; k0 += BKG) {
        __syncthreads();
        const bool more = (k0 + BKG < Cv);
        if (more) {
            #pragma unroll
            for (int i = 0; i < 2; i++) {
                ra[i] = *reinterpret_cast<const float4*>(&A[(size_t)(m0 + lr + 64 * i) * Cv + k0 + BKG + lc]);
                rw[i] = *reinterpret_cast<const float4*>(&W[(size_t)(n0 + lr + 64 * i) * Cv + k0 + BKG + lc]);
            }
        }

        #pragma unroll
        for (int k = 0; k < BKG; k++) {
            float a[8], b[8];
            *reinterpret_cast<float4*>(&a[0]) = *reinterpret_cast<float4*>(&As[cur][k][ty * 8]);
            *reinterpret_cast<float4*>(&a[4]) = *reinterpret_cast<float4*>(&As[cur][k][ty * 8 + 4]);
            *reinterpret_cast<float4*>(&b[0]) = *reinterpret_cast<float4*>(&Ws[cur][k][tx * 8]);
            *reinterpret_cast<float4*>(&b[4]) = *reinterpret_cast<float4*>(&Ws[cur][k][tx * 8 + 4]);
            #pragma unroll
            for (int i = 0; i < 8; i++)
                #pragma unroll
                for (int j = 0; j < 8; j++)
                    acc[i][j] = fmaf(a[i], b[j], acc[i][j]);
        }

        if (more) {
            const int nxt = cur ^ 1;
            #pragma unroll
            for (int i = 0; i < 2; i++)
                #pragma unroll
                for (int j = 0; j < 4; j++) {
                    As[nxt][lc + j][lr + 64 * i] = reinterpret_cast<float*>(&ra[i])[j];
                    Ws[nxt][lc + j][lr + 64 * i] = reinterpret_cast<float*>(&rw[i])[j];
                }
        }
        cur ^= 1;
    }

    // epilogue: bias + (optional) head-split, float4 stores
    #pragma unroll
    for (int i = 0; i < 8; i++) {
        const int m = m0 + ty * 8 + i;
        const int bb = m / Tv, t = m % Tv;
        #pragma unroll
        for (int jj = 0; jj < 8; jj += 4) {
            const int n = n0 + tx * 8 + jj;
            float4 bv4 = *reinterpret_cast<const float4*>(&bias[n]);
            float4 v;
            v.x = acc[i][jj + 0] + bv4.x;
            v.y = acc[i][jj + 1] + bv4.y;
            v.z = acc[i][jj + 2] + bv4.z;
            v.w = acc[i][jj + 3] + bv4.w;
            if (split_heads) {
                const int h = n >> 6, d = n & 63;
                *reinterpret_cast<float4*>(&out[(((size_t)(bb * Hn + h)) * Tv + t) * Dv + d]) = v;
            } else {
                *reinterpret_cast<float4*>(&out[(size_t)m * Cv + n]) = v;
            }
        }
    }
}

// ---------------------------------------------------------------------------
// Attention: per (b,h): Q tile 128 rows, stream 64-row K/V tiles.
// S = Q K^T; P = exp(S*scale) unnormalized; O += P V; final divide.
// 256 threads, 8x4 microtile, d-major Qs/Ks, s-major Ps/Vs.
// ---------------------------------------------------------------------------
#define AQ 128
#define AS 64
#define QP (AQ + 4)     // 132
#define SP (AS + 4)     // 68

__global__ __launch_bounds__(256, 2) void attn_kernel(float scale)
{
    extern __shared__ float sm[];
    float* Qs = sm;                       // [64][QP]  d-major
    float* Ks = Qs + 64 * QP;             // [64][SP]  d-major
    float* Vs = Ks + 64 * SP;             // [64][SP]  s-major (row s, col d)
    float* Ps = Vs + 64 * SP;             // [64][QP]  s-major (row s, col m)

    const int tid = threadIdx.x;
    const int tx = tid & 15;              // n dir (x4)
    const int ty = tid >> 4;              // m dir (x8)
    const int bh = blockIdx.y;
    const int q0 = blockIdx.x * AQ;

    const float* qb = g_q + (size_t)bh * Tv * Dv;
    const float* kb = g_k + (size_t)bh * Tv * Dv;
    const float* vb = g_v + (size_t)bh * Tv * Dv;

    // load Q tile (128x64) transposed -> Qs[d][m]
    {
        const int r = tid >> 1;                 // 0..127
        #pragma unroll
        for (int i = 0; i < 8; i++) {
            const int c = (tid & 1) * 32 + i * 4;
            float4 q4 = *reinterpret_cast<const float4*>(&qb[(size_t)(q0 + r) * Dv + c]);
            Qs[(c + 0) * QP + r] = q4.x;
            Qs[(c + 1) * QP + r] = q4.y;
            Qs[(c + 2) * QP + r] = q4.z;
            Qs[(c + 3) * QP + r] = q4.w;
        }
    }

    float o[8][4] = {};
    float rs[8] = {};

    for (int s0 = 0; s0 < Tv; s0 += AS) {
        __syncthreads();   // prev PV done (Vs/Ps free), Ks free
        // K tile (64x64) transposed -> Ks[d][s]; V tile direct -> Vs[s][d]
        {
            const int r = tid >> 2;             // 0..63
            #pragma unroll
            for (int i = 0; i < 4; i++) {
                const int c = (tid & 3) * 16 + i * 4;
                float4 k4 = *reinterpret_cast<const float4*>(&kb[(size_t)(s0 + r) * Dv + c]);
                Ks[(c + 0) * SP + r] = k4.x;
                Ks[(c + 1) * SP + r] = k4.y;
                Ks[(c + 2) * SP + r] = k4.z;
                Ks[(c + 3) * SP + r] = k4.w;
                *reinterpret_cast<float4*>(&Vs[r * SP + c]) =
                    *reinterpret_cast<const float4*>(&vb[(size_t)(s0 + r) * Dv + c]);
            }
        }
        __syncthreads();

        // S = Q K^T  (128x64, contraction over d=64)
        float s[8][4] = {};
        #pragma unroll 8
        for (int kk = 0; kk < 64; kk++) {
            float a[8], b[4];
            *reinterpret_cast<float4*>(&a[0]) = *reinterpret_cast<float4*>(&Qs[kk * QP + ty * 8]);
            *reinterpret_cast<float4*>(&a[4]) = *reinterpret_cast<float4*>(&Qs[kk * QP + ty * 8 + 4]);
            *reinterpret_cast<float4*>(&b[0]) = *reinterpret_cast<float4*>(&Ks[kk * SP + tx * 4]);
            #pragma unroll
            for (int i = 0; i < 8; i++)
                #pragma unroll
                for (int j = 0; j < 4; j++)
                    s[i][j] = fmaf(a[i], b[j], s[i][j]);
        }

        // P = exp(S*scale) -> Ps[s][m]; accumulate row sums
        #pragma unroll
        for (int i = 0; i < 8; i++)
            #pragma unroll
            for (int j = 0; j < 4; j++) {
                const float p = __expf(s[i][j] * scale);
                rs[i] += p;
                Ps[(tx * 4 + j) * QP + ty * 8 + i] = p;
            }
        __syncthreads();

        // O += P V  (128x64, contraction over s=64)
        #pragma unroll 8
        for (int ss = 0; ss < 64; ss++) {
            float p[8], b[4];
            *reinterpret_cast<float4*>(&p[0]) = *reinterpret_cast<float4*>(&Ps[ss * QP + ty * 8]);
            *reinterpret_cast<float4*>(&p[4]) = *reinterpret_cast<float4*>(&Ps[ss * QP + ty * 8 + 4]);
            *reinterpret_cast<float4*>(&b[0]) = *reinterpret_cast<float4*>(&Vs[ss * SP + tx * 4]);
            #pragma unroll
            for (int i = 0; i < 8; i++)
                #pragma unroll
                for (int j = 0; j < 4; j++)
                    o[i][j] = fmaf(p[i], b[j], o[i][j]);
        }
    }

    // reduce row sums across the 16 tx lanes sharing each row
    #pragma unroll
    for (int off = 8; off > 0; off >>= 1)
        #pragma unroll
        for (int i = 0; i < 8; i++)
            rs[i] += __shfl_xor_sync(0xffffffffu, rs[i], off, 16);

    const int b = bh / Hn, h = bh % Hn;
    #pragma unroll
    for (int i = 0; i < 8; i++) {
        const float inv = 1.0f / rs[i];
        const int t = q0 + ty * 8 + i;
        float4 v;
        v.x = o[i][0] * inv; v.y = o[i][1] * inv;
        v.z = o[i][2] * inv; v.w = o[i][3] * inv;
        *reinterpret_cast<float4*>(&g_y[((size_t)(b * Tv + t)) * Cv + h * Dv + tx * 4]) = v;
    }
}

// ---------------------------------------------------------------------------
extern "C" void kernel_launch(void* const* d_in, const int* in_sizes, int n_in,
                              void* d_out, int out_size)
{
    const float* x  = (const float*)d_in[0];
    const float* Wq = (const float*)d_in[1];
    const float* bq = (const float*)d_in[2];
    const float* Wk = (const float*)d_in[3];
    const float* bk = (const float*)d_in[4];
    const float* Wv = (const float*)d_in[5];
    const float* bv = (const float*)d_in[6];
    const float* Wp = (const float*)d_in[7];
    const float* bp = (const float*)d_in[8];
    float* out = (float*)d_out;

    float *qp, *kp, *vp, *yp;
    cudaGetSymbolAddress((void**)&qp, g_q);
    cudaGetSymbolAddress((void**)&kp, g_k);
    cudaGetSymbolAddress((void**)&vp, g_v);
    cudaGetSymbolAddress((void**)&yp, g_y);

    const int attn_smem = (64 * QP + 64 * SP + 64 * SP + 64 * QP) * (int)sizeof(float); // 102400
    cudaFuncSetAttribute(attn_kernel, cudaFuncAttributeMaxDynamicSharedMemorySize, attn_smem);

    dim3 gGrid(Cv / BN, Mv / BM);   // (8, 64)
    dim3 gBlk(256);

    gemm_nt_kernel<<<gGrid, gBlk>>>(x, Wq, bq, qp, 1);
    gemm_nt_kernel<<<gGrid, gBlk>>>(x, Wk, bk, kp, 1);
    gemm_nt_kernel<<<gGrid, gBlk>>>(x, Wv, bv, vp, 1);

    dim3 aGrid(Tv / AQ, Bv * Hn);   // (16, 64)
    attn_kernel<<<aGrid, gBlk, attn_smem>>>(0.125f);

    gemm_nt_kernel<<<gGrid, gBlk>>>(yp, Wp, bp, out, 0);
}

// round 4
// speedup vs baseline: 5.2866x; 2.2806x over previous
#include <cuda_runtime.h>
#include <cuda_bf16.h>
#include <cstdint>
#include <cstddef>

using bf16 = __nv_bfloat16;

constexpr int Bv = 4, Tv = 2048, Cv = 1024, Hn = 16, Dv = 64;
constexpr int Mv = Bv * Tv;   // 8192

// ---------------------------------------------------------------------------
// Scratch (device globals)
// ---------------------------------------------------------------------------
__device__ bf16 g_xh[(size_t)Mv * Cv], g_xl[(size_t)Mv * Cv];
__device__ bf16 g_wh[(size_t)4 * Cv * Cv], g_wl[(size_t)4 * Cv * Cv];
__device__ bf16 g_qh[(size_t)Mv * Cv], g_ql[(size_t)Mv * Cv];
__device__ bf16 g_kh[(size_t)Mv * Cv], g_kl[(size_t)Mv * Cv];
__device__ bf16 g_vh[(size_t)Mv * Cv], g_vl[(size_t)Mv * Cv];
__device__ bf16 g_yh[(size_t)Mv * Cv], g_yl[(size_t)Mv * Cv];

// ---------------------------------------------------------------------------
// Helpers
// ---------------------------------------------------------------------------
__device__ __forceinline__ uint32_t smem_u32(const void* p) {
    uint32_t a;
    asm("{ .reg .u64 t; cvta.to.shared.u64 t, %1; cvt.u32.u64 %0, t; }" : "=r"(a) : "l"(p));
    return a;
}
#define CP16(dst, src) \
    asm volatile("cp.async.cg.shared.global [%0], [%1], 16;" \
                 :: "r"(dst), "l"(__cvta_generic_to_global(src)) : "memory")
#define CPC() asm volatile("cp.async.commit_group;" ::: "memory")
#define CPW(n) asm volatile("cp.async.wait_group %0;" :: "n"(n) : "memory")

__device__ __forceinline__ void ldsm4(uint32_t r[4], uint32_t a) {
    asm volatile("ldmatrix.sync.aligned.m8n8.x4.shared.b16 {%0,%1,%2,%3}, [%4];"
                 : "=r"(r[0]), "=r"(r[1]), "=r"(r[2]), "=r"(r[3]) : "r"(a));
}
__device__ __forceinline__ void ldsm4t(uint32_t r[4], uint32_t a) {
    asm volatile("ldmatrix.sync.aligned.m8n8.x4.trans.shared.b16 {%0,%1,%2,%3}, [%4];"
                 : "=r"(r[0]), "=r"(r[1]), "=r"(r[2]), "=r"(r[3]) : "r"(a));
}
__device__ __forceinline__ void mma_bf16(float c[4], const uint32_t a[4],
                                         uint32_t b0, uint32_t b1) {
    asm volatile("mma.sync.aligned.m16n8k16.row.col.f32.bf16.bf16.f32 "
                 "{%0,%1,%2,%3}, {%4,%5,%6,%7}, {%8,%9}, {%0,%1,%2,%3};"
                 : "+f"(c[0]), "+f"(c[1]), "+f"(c[2]), "+f"(c[3])
                 : "r"(a[0]), "r"(a[1]), "r"(a[2]), "r"(a[3]), "r"(b0), "r"(b1));
}
__device__ __forceinline__ uint32_t pack2(bf16 x, bf16 y) {
    __nv_bfloat162 v = __halves2bfloat162(x, y);
    return *reinterpret_cast<uint32_t*>(&v);
}
// split v0,v1 -> packed hi u32, lo u32
__device__ __forceinline__ void split_pack(float v0, float v1, uint32_t& hi, uint32_t& lo) {
    bf16 h0 = __float2bfloat16(v0), h1 = __float2bfloat16(v1);
    bf16 l0 = __float2bfloat16(v0 - __bfloat162float(h0));
    bf16 l1 = __float2bfloat16(v1 - __bfloat162float(h1));
    hi = pack2(h0, h1);
    lo = pack2(l0, l1);
}

// ---------------------------------------------------------------------------
// split: fp32 -> bf16 hi + bf16 lo
// ---------------------------------------------------------------------------
__global__ __launch_bounds__(256) void split_kernel(
    const float* __restrict__ in, bf16* __restrict__ hi, bf16* __restrict__ lo, int n4)
{
    const int i = blockIdx.x * blockDim.x + threadIdx.x;
    if (i >= n4) return;
    float4 v = reinterpret_cast<const float4*>(in)[i];
    uint32_t h0, l0, h1, l1;
    split_pack(v.x, v.y, h0, l0);
    split_pack(v.z, v.w, h1, l1);
    reinterpret_cast<uint2*>(hi)[i] = make_uint2(h0, h1);
    reinterpret_cast<uint2*>(lo)[i] = make_uint2(l0, l1);
}

// ---------------------------------------------------------------------------
// mma GEMM: out[M,N] = (Ah+Al)[M,K] @ (Bh+Bl)[N,K]^T + bias
// CTA 128x128, kblock 32, 8 warps (4x2), warp tile 32x64.
// mode 0: fp32 out[m][n].  mode 1: bf16 hi/lo head-split out.
// ---------------------------------------------------------------------------
constexpr int GSTR = 40;                     // bf16 stride (80 B rows)
constexpr int GT_BYTES = 128 * GSTR * 2;     // 10240
constexpr int GSTAGE = 4 * GT_BYTES;         // 40960
constexpr int GEMM_SMEM = 2 * GSTAGE;        // 81920

__global__ __launch_bounds__(256, 1) void mma_gemm(
    const bf16* __restrict__ Ah, const bf16* __restrict__ Al,
    const bf16* __restrict__ Bh, const bf16* __restrict__ Bl,
    const float* __restrict__ bias,
    float* __restrict__ out32, bf16* __restrict__ oh, bf16* __restrict__ ol,
    int mode)
{
    extern __shared__ char smem[];
    const uint32_t sbb = smem_u32(smem);
    const int tid = threadIdx.x, lane = tid & 31, wid = tid >> 5;
    const int wm = wid & 3, wn = wid >> 2;
    const int m0 = blockIdx.y * 128, n0 = blockIdx.x * 128;

    auto g2s = [&](int stage, int kb) {
        const uint32_t st = sbb + stage * GSTAGE;
        const int k0 = kb * 32;
        #pragma unroll
        for (int j = 0; j < 2; j++) {
            const int idx = tid + j * 256;
            const int r = idx >> 2, kc = (idx & 3) * 8;
            const uint32_t so = (uint32_t)((r * GSTR + kc) * 2);
            CP16(st + 0 * GT_BYTES + so, Ah + (size_t)(m0 + r) * Cv + k0 + kc);
            CP16(st + 1 * GT_BYTES + so, Al + (size_t)(m0 + r) * Cv + k0 + kc);
            CP16(st + 2 * GT_BYTES + so, Bh + (size_t)(n0 + r) * Cv + k0 + kc);
            CP16(st + 3 * GT_BYTES + so, Bl + (size_t)(n0 + r) * Cv + k0 + kc);
        }
    };
    auto fad = [&](uint32_t tb, int rb, int cb) -> uint32_t {
        const int r = rb + (lane & 7) + 8 * ((lane >> 3) & 1);
        const int c = cb + 8 * (lane >> 4);
        return tb + (uint32_t)((r * GSTR + c) * 2);
    };

    float acc[2][8][4] = {};
    g2s(0, 0); CPC();
    g2s(1, 1); CPC();

    for (int kb = 0; kb < Cv / 32; kb++) {
        CPW(1); __syncthreads();
        const uint32_t st = sbb + (kb & 1) * GSTAGE;
        #pragma unroll
        for (int ks = 0; ks < 2; ks++) {
            uint32_t ah[2][4], al[2][4], bh4[4][4], bl4[4][4];
            #pragma unroll
            for (int mt = 0; mt < 2; mt++) {
                ldsm4(ah[mt], fad(st + 0 * GT_BYTES, wm * 32 + mt * 16, ks * 16));
                ldsm4(al[mt], fad(st + 1 * GT_BYTES, wm * 32 + mt * 16, ks * 16));
            }
            #pragma unroll
            for (int g = 0; g < 4; g++) {
                ldsm4(bh4[g], fad(st + 2 * GT_BYTES, wn * 64 + g * 16, ks * 16));
                ldsm4(bl4[g], fad(st + 3 * GT_BYTES, wn * 64 + g * 16, ks * 16));
            }
            #pragma unroll
            for (int nt = 0; nt < 8; nt++) {
                const int g = nt >> 1, o = nt & 1;
                const uint32_t b0h = bh4[g][o], b1h = bh4[g][o + 2];
                const uint32_t b0l = bl4[g][o], b1l = bl4[g][o + 2];
                #pragma unroll
                for (int mt = 0; mt < 2; mt++) {
                    mma_bf16(acc[mt][nt], ah[mt], b0h, b1h);
                    mma_bf16(acc[mt][nt], ah[mt], b0l, b1l);
                    mma_bf16(acc[mt][nt], al[mt], b0h, b1h);
                }
            }
        }
        __syncthreads();
        if (kb + 2 < Cv / 32) g2s(kb & 1, kb + 2);
        CPC();
    }

    // epilogue
    #pragma unroll
    for (int mt = 0; mt < 2; mt++) {
        const int mr = m0 + wm * 32 + mt * 16 + (lane >> 2);
        #pragma unroll
        for (int half = 0; half < 2; half++) {
            const int m = mr + half * 8;
            const int bb = m >> 11, t = m & (Tv - 1);
            #pragma unroll
            for (int nt = 0; nt < 8; nt++) {
                const int n = n0 + wn * 64 + nt * 8 + (lane & 3) * 2;
                const float v0 = acc[mt][nt][half * 2 + 0] + bias[n];
                const float v1 = acc[mt][nt][half * 2 + 1] + bias[n + 1];
                if (mode == 0) {
                    *reinterpret_cast<float2*>(out32 + (size_t)m * Cv + n) = make_float2(v0, v1);
                } else {
                    const int h = n >> 6, d = n & 63;
                    const size_t o = (((size_t)(bb * Hn + h)) * Tv + t) * Dv + d;
                    uint32_t hi, lo;
                    split_pack(v0, v1, hi, lo);
                    *reinterpret_cast<uint32_t*>(oh + o) = hi;
                    *reinterpret_cast<uint32_t*>(ol + o) = lo;
                }
            }
        }
    }
}

// ---------------------------------------------------------------------------
// mma attention: per (b,h), 128 q rows/CTA, 8 warps (16 rows each),
// stream 64-row K/V blocks. Unnormalized exp + deferred divide.
// ---------------------------------------------------------------------------
constexpr int VSTR = 72;                     // bf16 stride (144 B rows)
constexpr int QT_BYTES = 128 * VSTR * 2;     // 18432
constexpr int KT_BYTES = 64 * VSTR * 2;      // 9216
constexpr int ASTAGE = 4 * KT_BYTES;         // 36864
constexpr int ATT_SMEM = 2 * QT_BYTES + 2 * ASTAGE;   // 110592

__global__ __launch_bounds__(256, 1) void mma_attn()
{
    extern __shared__ char smem[];
    const uint32_t sbb = smem_u32(smem);
    const int tid = threadIdx.x, lane = tid & 31, wid = tid >> 5;
    const int bh = blockIdx.y, q0 = blockIdx.x * 128;

    const bf16* qh = g_qh + (size_t)bh * Tv * Dv;
    const bf16* ql = g_ql + (size_t)bh * Tv * Dv;
    const bf16* kh = g_kh + (size_t)bh * Tv * Dv;
    const bf16* kl = g_kl + (size_t)bh * Tv * Dv;
    const bf16* vh = g_vh + (size_t)bh * Tv * Dv;
    const bf16* vl = g_vl + (size_t)bh * Tv * Dv;

    const uint32_t QH = sbb, QL = sbb + QT_BYTES, ST0 = sbb + 2 * QT_BYTES;

    // Q tiles (128x64 hi/lo)
    #pragma unroll
    for (int j = 0; j < 4; j++) {
        const int idx = tid + j * 256;
        const int r = idx >> 3, dc = (idx & 7) * 8;
        const uint32_t so = (uint32_t)((r * VSTR + dc) * 2);
        CP16(QH + so, qh + (size_t)(q0 + r) * Dv + dc);
        CP16(QL + so, ql + (size_t)(q0 + r) * Dv + dc);
    }
    CPC();

    auto g2s = [&](int stage, int blk) {
        const uint32_t st = ST0 + stage * ASTAGE;
        const int s0 = blk * 64;
        #pragma unroll
        for (int j = 0; j < 2; j++) {
            const int idx = tid + j * 256;
            const int r = idx >> 3, dc = (idx & 7) * 8;
            const uint32_t so = (uint32_t)((r * VSTR + dc) * 2);
            CP16(st + 0 * KT_BYTES + so, kh + (size_t)(s0 + r) * Dv + dc);
            CP16(st + 1 * KT_BYTES + so, kl + (size_t)(s0 + r) * Dv + dc);
            CP16(st + 2 * KT_BYTES + so, vh + (size_t)(s0 + r) * Dv + dc);
            CP16(st + 3 * KT_BYTES + so, vl + (size_t)(s0 + r) * Dv + dc);
        }
    };
    auto fad = [&](uint32_t tb, int rb, int cb) -> uint32_t {
        const int r = rb + (lane & 7) + 8 * ((lane >> 3) & 1);
        const int c = cb + 8 * (lane >> 4);
        return tb + (uint32_t)((r * VSTR + c) * 2);
    };

    g2s(0, 0); CPC();
    g2s(1, 1); CPC();
    CPW(2); __syncthreads();   // Q ready

    uint32_t qfh[4][4], qfl[4][4];
    #pragma unroll
    for (int ks = 0; ks < 4; ks++) {
        ldsm4(qfh[ks], fad(QH, wid * 16, ks * 16));
        ldsm4(qfl[ks], fad(QL, wid * 16, ks * 16));
    }

    float oacc[8][4] = {};
    float rs0 = 0.f, rs1 = 0.f;

    for (int blk = 0; blk < Tv / 64; blk++) {
        CPW(1); __syncthreads();
        const uint32_t st = ST0 + (blk & 1) * ASTAGE;

        // S = Q K^T
        float sacc[8][4] = {};
        #pragma unroll
        for (int ks = 0; ks < 4; ks++) {
            uint32_t kfh[4][4], kfl[4][4];
            #pragma unroll
            for (int g = 0; g < 4; g++) {
                ldsm4(kfh[g], fad(st + 0 * KT_BYTES, g * 16, ks * 16));
                ldsm4(kfl[g], fad(st + 1 * KT_BYTES, g * 16, ks * 16));
            }
            #pragma unroll
            for (int nt = 0; nt < 8; nt++) {
                const int g = nt >> 1, o = nt & 1;
                mma_bf16(sacc[nt], qfh[ks], kfh[g][o], kfh[g][o + 2]);
                mma_bf16(sacc[nt], qfh[ks], kfl[g][o], kfl[g][o + 2]);
                mma_bf16(sacc[nt], qfl[ks], kfh[g][o], kfh[g][o + 2]);
            }
        }

        // P = exp(S * scale), split+pack into A-fragments
        uint32_t pah[4][4], pal[4][4];
        #pragma unroll
        for (int nt = 0; nt < 8; nt++) {
            const float p0 = __expf(sacc[nt][0] * 0.125f);
            const float p1 = __expf(sacc[nt][1] * 0.125f);
            const float p2 = __expf(sacc[nt][2] * 0.125f);
            const float p3 = __expf(sacc[nt][3] * 0.125f);
            rs0 += p0 + p1;
            rs1 += p2 + p3;
            const int jj = nt >> 1, off = (nt & 1) * 2;
            split_pack(p0, p1, pah[jj][off], pal[jj][off]);
            split_pack(p2, p3, pah[jj][off + 1], pal[jj][off + 1]);
        }

        // O += P V
        #pragma unroll
        for (int ks = 0; ks < 4; ks++) {
            uint32_t vfh[4][4], vfl[4][4];
            #pragma unroll
            for (int g = 0; g < 4; g++) {
                ldsm4t(vfh[g], fad(st + 2 * KT_BYTES, ks * 16, g * 16));
                ldsm4t(vfl[g], fad(st + 3 * KT_BYTES, ks * 16, g * 16));
            }
            #pragma unroll
            for (int dt = 0; dt < 8; dt++) {
                const int g = dt >> 1, o = (dt & 1) * 2;
                mma_bf16(oacc[dt], pah[ks], vfh[g][o], vfh[g][o + 1]);
                mma_bf16(oacc[dt], pah[ks], vfl[g][o], vfl[g][o + 1]);
                mma_bf16(oacc[dt], pal[ks], vfh[g][o], vfh[g][o + 1]);
            }
        }

        __syncthreads();
        if (blk + 2 < Tv / 64) g2s(blk & 1, blk + 2);
        CPC();
    }

    // reduce row sums within quad (lanes sharing a row)
    rs0 += __shfl_xor_sync(0xffffffffu, rs0, 1);
    rs0 += __shfl_xor_sync(0xffffffffu, rs0, 2);
    rs1 += __shfl_xor_sync(0xffffffffu, rs1, 1);
    rs1 += __shfl_xor_sync(0xffffffffu, rs1, 2);
    const float inv0 = 1.0f / rs0, inv1 = 1.0f / rs1;

    const int b = bh >> 4, h = bh & 15;
    const int t0 = q0 + wid * 16 + (lane >> 2);
    #pragma unroll
    for (int dt = 0; dt < 8; dt++) {
        const int col = h * 64 + dt * 8 + (lane & 3) * 2;
        uint32_t hi, lo;
        split_pack(oacc[dt][0] * inv0, oacc[dt][1] * inv0, hi, lo);
        size_t o = (size_t)(b * Tv + t0) * Cv + col;
        *reinterpret_cast<uint32_t*>(g_yh + o) = hi;
        *reinterpret_cast<uint32_t*>(g_yl + o) = lo;
        split_pack(oacc[dt][2] * inv1, oacc[dt][3] * inv1, hi, lo);
        o = (size_t)(b * Tv + t0 + 8) * Cv + col;
        *reinterpret_cast<uint32_t*>(g_yh + o) = hi;
        *reinterpret_cast<uint32_t*>(g_yl + o) = lo;
    }
}

// ---------------------------------------------------------------------------
extern "C" void kernel_launch(void* const* d_in, const int* in_sizes, int n_in,
                              void* d_out, int out_size)
{
    const float* x  = (const float*)d_in[0];
    const float* Wq = (const float*)d_in[1];
    const float* bq = (const float*)d_in[2];
    const float* Wk = (const float*)d_in[3];
    const float* bk = (const float*)d_in[4];
    const float* Wv = (const float*)d_in[5];
    const float* bv = (const float*)d_in[6];
    const float* Wp = (const float*)d_in[7];
    const float* bp = (const float*)d_in[8];
    float* out = (float*)d_out;

    bf16 *xh, *xl, *wh, *wl, *qh, *ql, *kh, *kl, *vh, *vl, *yh, *yl;
    cudaGetSymbolAddress((void**)&xh, g_xh); cudaGetSymbolAddress((void**)&xl, g_xl);
    cudaGetSymbolAddress((void**)&wh, g_wh); cudaGetSymbolAddress((void**)&wl, g_wl);
    cudaGetSymbolAddress((void**)&qh, g_qh); cudaGetSymbolAddress((void**)&ql, g_ql);
    cudaGetSymbolAddress((void**)&kh, g_kh); cudaGetSymbolAddress((void**)&kl, g_kl);
    cudaGetSymbolAddress((void**)&vh, g_vh); cudaGetSymbolAddress((void**)&vl, g_vl);
    cudaGetSymbolAddress((void**)&yh, g_yh); cudaGetSymbolAddress((void**)&yl, g_yl);

    cudaFuncSetAttribute(mma_gemm, cudaFuncAttributeMaxDynamicSharedMemorySize, GEMM_SMEM);
    cudaFuncSetAttribute(mma_attn, cudaFuncAttributeMaxDynamicSharedMemorySize, ATT_SMEM);

    const size_t WN = (size_t)Cv * Cv;
    const int xs4 = Mv * Cv / 4, ws4 = (int)(WN / 4);

    split_kernel<<<(xs4 + 255) / 256, 256>>>(x, xh, xl, xs4);
    split_kernel<<<(ws4 + 255) / 256, 256>>>(Wq, wh + 0 * WN, wl + 0 * WN, ws4);
    split_kernel<<<(ws4 + 255) / 256, 256>>>(Wk, wh + 1 * WN, wl + 1 * WN, ws4);
    split_kernel<<<(ws4 + 255) / 256, 256>>>(Wv, wh + 2 * WN, wl + 2 * WN, ws4);
    split_kernel<<<(ws4 + 255) / 256, 256>>>(Wp, wh + 3 * WN, wl + 3 * WN, ws4);

    dim3 gGrid(Cv / 128, Mv / 128);   // (8, 64)
    mma_gemm<<<gGrid, 256, GEMM_SMEM>>>(xh, xl, wh + 0 * WN, wl + 0 * WN, bq, nullptr, qh, ql, 1);
    mma_gemm<<<gGrid, 256, GEMM_SMEM>>>(xh, xl, wh + 1 * WN, wl + 1 * WN, bk, nullptr, kh, kl, 1);
    mma_gemm<<<gGrid, 256, GEMM_SMEM>>>(xh, xl, wh + 2 * WN, wl + 2 * WN, bv, nullptr, vh, vl, 1);

    dim3 aGrid(Tv / 128, Bv * Hn);    // (16, 64)
    mma_attn<<<aGrid, 256, ATT_SMEM>>>();

    mma_gemm<<<gGrid, 256, GEMM_SMEM>>>(yh, yl, wh + 3 * WN, wl + 3 * WN, bp, out, nullptr, nullptr, 0);
}

// round 6
// speedup vs baseline: 7.9628x; 1.5062x over previous
#include <cuda_runtime.h>
#include <cuda_fp16.h>
#include <cstdint>
#include <cstddef>

using fp16 = __half;

constexpr int Bv = 4, Tv = 2048, Cv = 1024, Hn = 16, Dv = 64;
constexpr int Mv = Bv * Tv;   // 8192

// ---------------------------------------------------------------------------
// Scratch (device globals)
// ---------------------------------------------------------------------------
__device__ fp16 g_xh[(size_t)Mv * Cv], g_xl[(size_t)Mv * Cv];
__device__ fp16 g_wh[(size_t)4 * Cv * Cv];
__device__ fp16 g_qh[(size_t)Mv * Cv], g_ql[(size_t)Mv * Cv];
__device__ fp16 g_kh[(size_t)Mv * Cv], g_kl[(size_t)Mv * Cv];   // kl: sink only
__device__ fp16 g_vh[(size_t)Mv * Cv], g_vl[(size_t)Mv * Cv];   // vl: sink only
__device__ fp16 g_yh[(size_t)Mv * Cv], g_yl[(size_t)Mv * Cv];

// ---------------------------------------------------------------------------
// Helpers
// ---------------------------------------------------------------------------
__device__ __forceinline__ uint32_t smem_u32(const void* p) {
    uint32_t a;
    asm("{ .reg .u64 t; cvta.to.shared.u64 t, %1; cvt.u32.u64 %0, t; }" : "=r"(a) : "l"(p));
    return a;
}
#define CP16(dst, src) \
    asm volatile("cp.async.cg.shared.global [%0], [%1], 16;" \
                 :: "r"(dst), "l"(__cvta_generic_to_global(src)) : "memory")
#define CPC() asm volatile("cp.async.commit_group;" ::: "memory")
#define CPW(n) asm volatile("cp.async.wait_group %0;" :: "n"(n) : "memory")

__device__ __forceinline__ void ldsm4(uint32_t r[4], uint32_t a) {
    asm volatile("ldmatrix.sync.aligned.m8n8.x4.shared.b16 {%0,%1,%2,%3}, [%4];"
                 : "=r"(r[0]), "=r"(r[1]), "=r"(r[2]), "=r"(r[3]) : "r"(a));
}
__device__ __forceinline__ void ldsm4t(uint32_t r[4], uint32_t a) {
    asm volatile("ldmatrix.sync.aligned.m8n8.x4.trans.shared.b16 {%0,%1,%2,%3}, [%4];"
                 : "=r"(r[0]), "=r"(r[1]), "=r"(r[2]), "=r"(r[3]) : "r"(a));
}
__device__ __forceinline__ void mma_f16(float c[4], const uint32_t a[4],
                                        uint32_t b0, uint32_t b1) {
    asm volatile("mma.sync.aligned.m16n8k16.row.col.f32.f16.f16.f32 "
                 "{%0,%1,%2,%3}, {%4,%5,%6,%7}, {%8,%9}, {%0,%1,%2,%3};"
                 : "+f"(c[0]), "+f"(c[1]), "+f"(c[2]), "+f"(c[3])
                 : "r"(a[0]), "r"(a[1]), "r"(a[2]), "r"(a[3]), "r"(b0), "r"(b1));
}
__device__ __forceinline__ uint32_t pack2h(fp16 x, fp16 y) {
    __half2 v = __halves2half2(x, y);
    return *reinterpret_cast<uint32_t*>(&v);
}
__device__ __forceinline__ void split_pack(float v0, float v1, uint32_t& hi, uint32_t& lo) {
    fp16 h0 = __float2half_rn(v0), h1 = __float2half_rn(v1);
    fp16 l0 = __float2half_rn(v0 - __half2float(h0));
    fp16 l1 = __float2half_rn(v1 - __half2float(h1));
    hi = pack2h(h0, h1);
    lo = pack2h(l0, l1);
}

// ---------------------------------------------------------------------------
// split fp32 -> fp16 hi/lo ; convert fp32 -> fp16
// ---------------------------------------------------------------------------
__global__ __launch_bounds__(256) void split_kernel(
    const float* __restrict__ in, fp16* __restrict__ hi, fp16* __restrict__ lo, int n4)
{
    const int i = blockIdx.x * blockDim.x + threadIdx.x;
    if (i >= n4) return;
    float4 v = reinterpret_cast<const float4*>(in)[i];
    uint32_t h0, l0, h1, l1;
    split_pack(v.x, v.y, h0, l0);
    split_pack(v.z, v.w, h1, l1);
    reinterpret_cast<uint2*>(hi)[i] = make_uint2(h0, h1);
    reinterpret_cast<uint2*>(lo)[i] = make_uint2(l0, l1);
}

__global__ __launch_bounds__(256) void cvt_kernel(
    const float* __restrict__ in, fp16* __restrict__ out, int n4)
{
    const int i = blockIdx.x * blockDim.x + threadIdx.x;
    if (i >= n4) return;
    float4 v = reinterpret_cast<const float4*>(in)[i];
    uint32_t h0 = pack2h(__float2half_rn(v.x), __float2half_rn(v.y));
    uint32_t h1 = pack2h(__float2half_rn(v.z), __float2half_rn(v.w));
    reinterpret_cast<uint2*>(out)[i] = make_uint2(h0, h1);
}

// ---------------------------------------------------------------------------
// mma GEMM: out[M,N] = (Ah+Al)[M,K] @ Bh[N,K]^T + bias
// CTA 128x128, kblock 32, 8 warps (4x2), warp tile 32x64, 2 products.
// mode 0: fp32 out.  mode 1: fp16 hi/lo head-split out.
// ---------------------------------------------------------------------------
constexpr int GSTR = 40;                     // fp16 stride (80 B rows)
constexpr int GT_BYTES = 128 * GSTR * 2;     // 10240
constexpr int GSTAGE = 3 * GT_BYTES;         // Ah, Al, Bh = 30720
constexpr int GEMM_SMEM = 2 * GSTAGE;        // 61440

__global__ __launch_bounds__(256) void mma_gemm(
    const fp16* __restrict__ Ah, const fp16* __restrict__ Al,
    const fp16* __restrict__ Bh, const float* __restrict__ bias,
    float* __restrict__ out32, fp16* __restrict__ oh, fp16* __restrict__ ol,
    int mode)
{
    extern __shared__ char smem[];
    const uint32_t sbb = smem_u32(smem);
    const int tid = threadIdx.x, lane = tid & 31, wid = tid >> 5;
    const int wm = wid & 3, wn = wid >> 2;
    const int m0 = blockIdx.y * 128, n0 = blockIdx.x * 128;

    auto g2s = [&](int stage, int kb) {
        const uint32_t st = sbb + stage * GSTAGE;
        const int k0 = kb * 32;
        #pragma unroll
        for (int j = 0; j < 2; j++) {
            const int idx = tid + j * 256;
            const int r = idx >> 2, kc = (idx & 3) * 8;
            const uint32_t so = (uint32_t)((r * GSTR + kc) * 2);
            CP16(st + 0 * GT_BYTES + so, Ah + (size_t)(m0 + r) * Cv + k0 + kc);
            CP16(st + 1 * GT_BYTES + so, Al + (size_t)(m0 + r) * Cv + k0 + kc);
            CP16(st + 2 * GT_BYTES + so, Bh + (size_t)(n0 + r) * Cv + k0 + kc);
        }
    };
    auto fad = [&](uint32_t tb, int rb, int cb) -> uint32_t {
        const int r = rb + (lane & 7) + 8 * ((lane >> 3) & 1);
        const int c = cb + 8 * (lane >> 4);
        return tb + (uint32_t)((r * GSTR + c) * 2);
    };

    float acc[2][8][4] = {};
    g2s(0, 0); CPC();
    g2s(1, 1); CPC();

    for (int kb = 0; kb < Cv / 32; kb++) {
        CPW(1); __syncthreads();
        const uint32_t st = sbb + (kb & 1) * GSTAGE;
        #pragma unroll
        for (int ks = 0; ks < 2; ks++) {
            uint32_t ah[2][4], al[2][4], bh4[4][4];
            #pragma unroll
            for (int mt = 0; mt < 2; mt++) {
                ldsm4(ah[mt], fad(st + 0 * GT_BYTES, wm * 32 + mt * 16, ks * 16));
                ldsm4(al[mt], fad(st + 1 * GT_BYTES, wm * 32 + mt * 16, ks * 16));
            }
            #pragma unroll
            for (int g = 0; g < 4; g++)
                ldsm4(bh4[g], fad(st + 2 * GT_BYTES, wn * 64 + g * 16, ks * 16));
            #pragma unroll
            for (int nt = 0; nt < 8; nt++) {
                const int g = nt >> 1, o = nt & 1;
                const uint32_t b0 = bh4[g][o], b1 = bh4[g][o + 2];
                #pragma unroll
                for (int mt = 0; mt < 2; mt++) {
                    mma_f16(acc[mt][nt], ah[mt], b0, b1);
                    mma_f16(acc[mt][nt], al[mt], b0, b1);
                }
            }
        }
        __syncthreads();
        if (kb + 2 < Cv / 32) g2s(kb & 1, kb + 2);
        CPC();
    }

    // epilogue
    #pragma unroll
    for (int mt = 0; mt < 2; mt++) {
        const int mr = m0 + wm * 32 + mt * 16 + (lane >> 2);
        #pragma unroll
        for (int half = 0; half < 2; half++) {
            const int m = mr + half * 8;
            const int bb = m >> 11, t = m & (Tv - 1);
            #pragma unroll
            for (int nt = 0; nt < 8; nt++) {
                const int n = n0 + wn * 64 + nt * 8 + (lane & 3) * 2;
                const float v0 = acc[mt][nt][half * 2 + 0] + bias[n];
                const float v1 = acc[mt][nt][half * 2 + 1] + bias[n + 1];
                if (mode == 0) {
                    *reinterpret_cast<float2*>(out32 + (size_t)m * Cv + n) = make_float2(v0, v1);
                } else {
                    const int h = n >> 6, d = n & 63;
                    const size_t o = (((size_t)(bb * Hn + h)) * Tv + t) * Dv + d;
                    uint32_t hi, lo;
                    split_pack(v0, v1, hi, lo);
                    *reinterpret_cast<uint32_t*>(oh + o) = hi;
                    *reinterpret_cast<uint32_t*>(ol + o) = lo;
                }
            }
        }
    }
}

// ---------------------------------------------------------------------------
// mma attention: per (b,h), 128 q rows/CTA, 8 warps, 64-row K/V blocks.
// S = (Qh+Ql) Kh^T ; P = exp(S/8) ; O += (Ph+Pl) Vh ; deferred divide.
// ---------------------------------------------------------------------------
constexpr int VSTR = 72;                     // fp16 stride (144 B rows)
constexpr int QT_BYTES = 128 * VSTR * 2;     // 18432
constexpr int KT_BYTES = 64 * VSTR * 2;      // 9216
constexpr int ASTAGE = 2 * KT_BYTES;         // Kh, Vh = 18432
constexpr int ATT_SMEM = 2 * QT_BYTES + 2 * ASTAGE;   // 73728

__global__ __launch_bounds__(256) void mma_attn()
{
    extern __shared__ char smem[];
    const uint32_t sbb = smem_u32(smem);
    const int tid = threadIdx.x, lane = tid & 31, wid = tid >> 5;
    const int bh = blockIdx.y, q0 = blockIdx.x * 128;

    const fp16* qh = g_qh + (size_t)bh * Tv * Dv;
    const fp16* ql = g_ql + (size_t)bh * Tv * Dv;
    const fp16* kh = g_kh + (size_t)bh * Tv * Dv;
    const fp16* vh = g_vh + (size_t)bh * Tv * Dv;

    const uint32_t QH = sbb, QL = sbb + QT_BYTES, ST0 = sbb + 2 * QT_BYTES;

    #pragma unroll
    for (int j = 0; j < 4; j++) {
        const int idx = tid + j * 256;
        const int r = idx >> 3, dc = (idx & 7) * 8;
        const uint32_t so = (uint32_t)((r * VSTR + dc) * 2);
        CP16(QH + so, qh + (size_t)(q0 + r) * Dv + dc);
        CP16(QL + so, ql + (size_t)(q0 + r) * Dv + dc);
    }
    CPC();

    // FIXED loader: 1024 cp.async per stage — idx<512 -> K rows 0..63,
    // idx>=512 -> V rows 0..63. Branch is uniform per unrolled j.
    auto g2s = [&](int stage, int blk) {
        const uint32_t st = ST0 + stage * ASTAGE;
        const int s0 = blk * 64;
        #pragma unroll
        for (int j = 0; j < 4; j++) {
            const int idx = tid + j * 256;          // 0..1023
            const int r = (idx >> 3) & 63;
            const int dc = (idx & 7) * 8;
            const uint32_t so = (uint32_t)((r * VSTR + dc) * 2);
            if (idx < 512) CP16(st + so,            kh + (size_t)(s0 + r) * Dv + dc);
            else           CP16(st + KT_BYTES + so, vh + (size_t)(s0 + r) * Dv + dc);
        }
    };
    auto fad = [&](uint32_t tb, int rb, int cb) -> uint32_t {
        const int r = rb + (lane & 7) + 8 * ((lane >> 3) & 1);
        const int c = cb + 8 * (lane >> 4);
        return tb + (uint32_t)((r * VSTR + c) * 2);
    };

    g2s(0, 0); CPC();
    g2s(1, 1); CPC();
    CPW(2); __syncthreads();   // Q ready

    uint32_t qfh[4][4], qfl[4][4];
    #pragma unroll
    for (int ks = 0; ks < 4; ks++) {
        ldsm4(qfh[ks], fad(QH, wid * 16, ks * 16));
        ldsm4(qfl[ks], fad(QL, wid * 16, ks * 16));
    }

    float oacc[8][4] = {};
    float rs0 = 0.f, rs1 = 0.f;

    for (int blk = 0; blk < Tv / 64; blk++) {
        CPW(1); __syncthreads();
        const uint32_t st = ST0 + (blk & 1) * ASTAGE;

        // S = Q K^T
        float sacc[8][4] = {};
        #pragma unroll
        for (int ks = 0; ks < 4; ks++) {
            uint32_t kf[4][4];
            #pragma unroll
            for (int g = 0; g < 4; g++)
                ldsm4(kf[g], fad(st, g * 16, ks * 16));
            #pragma unroll
            for (int nt = 0; nt < 8; nt++) {
                const int g = nt >> 1, o = nt & 1;
                mma_f16(sacc[nt], qfh[ks], kf[g][o], kf[g][o + 2]);
                mma_f16(sacc[nt], qfl[ks], kf[g][o], kf[g][o + 2]);
            }
        }

        // P = exp(S/8) -> hi/lo fragments
        uint32_t pah[4][4], pal[4][4];
        #pragma unroll
        for (int nt = 0; nt < 8; nt++) {
            const float p0 = __expf(sacc[nt][0] * 0.125f);
            const float p1 = __expf(sacc[nt][1] * 0.125f);
            const float p2 = __expf(sacc[nt][2] * 0.125f);
            const float p3 = __expf(sacc[nt][3] * 0.125f);
            rs0 += p0 + p1;
            rs1 += p2 + p3;
            const int jj = nt >> 1, off = (nt & 1) * 2;
            split_pack(p0, p1, pah[jj][off], pal[jj][off]);
            split_pack(p2, p3, pah[jj][off + 1], pal[jj][off + 1]);
        }

        // O += P V
        #pragma unroll
        for (int ks = 0; ks < 4; ks++) {
            uint32_t vf[4][4];
            #pragma unroll
            for (int g = 0; g < 4; g++)
                ldsm4t(vf[g], fad(st + KT_BYTES, ks * 16, g * 16));
            #pragma unroll
            for (int dt = 0; dt < 8; dt++) {
                const int g = dt >> 1, o = (dt & 1) * 2;
                mma_f16(oacc[dt], pah[ks], vf[g][o], vf[g][o + 1]);
                mma_f16(oacc[dt], pal[ks], vf[g][o], vf[g][o + 1]);
            }
        }

        __syncthreads();
        if (blk + 2 < Tv / 64) g2s(blk & 1, blk + 2);
        CPC();
    }

    rs0 += __shfl_xor_sync(0xffffffffu, rs0, 1);
    rs0 += __shfl_xor_sync(0xffffffffu, rs0, 2);
    rs1 += __shfl_xor_sync(0xffffffffu, rs1, 1);
    rs1 += __shfl_xor_sync(0xffffffffu, rs1, 2);
    const float inv0 = 1.0f / rs0, inv1 = 1.0f / rs1;

    const int b = bh >> 4, h = bh & 15;
    const int t0 = q0 + wid * 16 + (lane >> 2);
    #pragma unroll
    for (int dt = 0; dt < 8; dt++) {
        const int col = h * 64 + dt * 8 + (lane & 3) * 2;
        uint32_t hi, lo;
        split_pack(oacc[dt][0] * inv0, oacc[dt][1] * inv0, hi, lo);
        size_t o = (size_t)(b * Tv + t0) * Cv + col;
        *reinterpret_cast<uint32_t*>(g_yh + o) = hi;
        *reinterpret_cast<uint32_t*>(g_yl + o) = lo;
        split_pack(oacc[dt][2] * inv1, oacc[dt][3] * inv1, hi, lo);
        o = (size_t)(b * Tv + t0 + 8) * Cv + col;
        *reinterpret_cast<uint32_t*>(g_yh + o) = hi;
        *reinterpret_cast<uint32_t*>(g_yl + o) = lo;
    }
}

// ---------------------------------------------------------------------------
extern "C" void kernel_launch(void* const* d_in, const int* in_sizes, int n_in,
                              void* d_out, int out_size)
{
    const float* x  = (const float*)d_in[0];
    const float* Wq = (const float*)d_in[1];
    const float* bq = (const float*)d_in[2];
    const float* Wk = (const float*)d_in[3];
    const float* bk = (const float*)d_in[4];
    const float* Wv = (const float*)d_in[5];
    const float* bv = (const float*)d_in[6];
    const float* Wp = (const float*)d_in[7];
    const float* bp = (const float*)d_in[8];
    float* out = (float*)d_out;

    fp16 *xh, *xl, *wh, *qh, *ql, *kh, *kl, *vh, *vl, *yh, *yl;
    cudaGetSymbolAddress((void**)&xh, g_xh); cudaGetSymbolAddress((void**)&xl, g_xl);
    cudaGetSymbolAddress((void**)&wh, g_wh);
    cudaGetSymbolAddress((void**)&qh, g_qh); cudaGetSymbolAddress((void**)&ql, g_ql);
    cudaGetSymbolAddress((void**)&kh, g_kh); cudaGetSymbolAddress((void**)&kl, g_kl);
    cudaGetSymbolAddress((void**)&vh, g_vh); cudaGetSymbolAddress((void**)&vl, g_vl);
    cudaGetSymbolAddress((void**)&yh, g_yh); cudaGetSymbolAddress((void**)&yl, g_yl);

    cudaFuncSetAttribute(mma_gemm, cudaFuncAttributeMaxDynamicSharedMemorySize, GEMM_SMEM);
    cudaFuncSetAttribute(mma_attn, cudaFuncAttributeMaxDynamicSharedMemorySize, ATT_SMEM);

    const size_t WN = (size_t)Cv * Cv;
    const int xs4 = Mv * Cv / 4, ws4 = (int)(WN / 4);

    split_kernel<<<(xs4 + 255) / 256, 256>>>(x, xh, xl, xs4);
    cvt_kernel<<<(ws4 + 255) / 256, 256>>>(Wq, wh + 0 * WN, ws4);
    cvt_kernel<<<(ws4 + 255) / 256, 256>>>(Wk, wh + 1 * WN, ws4);
    cvt_kernel<<<(ws4 + 255) / 256, 256>>>(Wv, wh + 2 * WN, ws4);
    cvt_kernel<<<(ws4 + 255) / 256, 256>>>(Wp, wh + 3 * WN, ws4);

    dim3 gGrid(Cv / 128, Mv / 128);   // (8, 64)
    mma_gemm<<<gGrid, 256, GEMM_SMEM>>>(xh, xl, wh + 0 * WN, bq, nullptr, qh, ql, 1);
    mma_gemm<<<gGrid, 256, GEMM_SMEM>>>(xh, xl, wh + 1 * WN, bk, nullptr, kh, kl, 1);
    mma_gemm<<<gGrid, 256, GEMM_SMEM>>>(xh, xl, wh + 2 * WN, bv, nullptr, vh, vl, 1);

    dim3 aGrid(Tv / 128, Bv * Hn);    // (16, 64)
    mma_attn<<<aGrid, 256, ATT_SMEM>>>();

    mma_gemm<<<gGrid, 256, GEMM_SMEM>>>(yh, yl, wh + 3 * WN, bp, out, nullptr, nullptr, 0);
}

// round 7
// speedup vs baseline: 9.7821x; 1.2285x over previous
#include <cuda_runtime.h>
#include <cuda_fp16.h>
#include <cstdint>
#include <cstddef>

using fp16 = __half;

constexpr int Bv = 4, Tv = 2048, Cv = 1024, Hn = 16, Dv = 64;
constexpr int Mv = Bv * Tv;   // 8192

// ---------------------------------------------------------------------------
// Scratch (device globals)
// ---------------------------------------------------------------------------
__device__ fp16 g_xh[(size_t)Mv * Cv], g_xl[(size_t)Mv * Cv];
__device__ fp16 g_wh[(size_t)4 * Cv * Cv];
__device__ fp16 g_qh[(size_t)Mv * Cv], g_ql[(size_t)Mv * Cv];
__device__ fp16 g_kh[(size_t)Mv * Cv];
__device__ fp16 g_vh[(size_t)Mv * Cv];
__device__ fp16 g_yh[(size_t)Mv * Cv], g_yl[(size_t)Mv * Cv];

// ---------------------------------------------------------------------------
// Helpers
// ---------------------------------------------------------------------------
__device__ __forceinline__ uint32_t smem_u32(const void* p) {
    uint32_t a;
    asm("{ .reg .u64 t; cvta.to.shared.u64 t, %1; cvt.u32.u64 %0, t; }" : "=r"(a) : "l"(p));
    return a;
}
#define CP16(dst, src) \
    asm volatile("cp.async.cg.shared.global [%0], [%1], 16;" \
                 :: "r"(dst), "l"(__cvta_generic_to_global(src)) : "memory")
#define CPC() asm volatile("cp.async.commit_group;" ::: "memory")
#define CPW(n) asm volatile("cp.async.wait_group %0;" :: "n"(n) : "memory")

__device__ __forceinline__ void ldsm4(uint32_t r[4], uint32_t a) {
    asm volatile("ldmatrix.sync.aligned.m8n8.x4.shared.b16 {%0,%1,%2,%3}, [%4];"
                 : "=r"(r[0]), "=r"(r[1]), "=r"(r[2]), "=r"(r[3]) : "r"(a));
}
__device__ __forceinline__ void ldsm4t(uint32_t r[4], uint32_t a) {
    asm volatile("ldmatrix.sync.aligned.m8n8.x4.trans.shared.b16 {%0,%1,%2,%3}, [%4];"
                 : "=r"(r[0]), "=r"(r[1]), "=r"(r[2]), "=r"(r[3]) : "r"(a));
}
__device__ __forceinline__ void mma_f16(float c[4], const uint32_t a[4],
                                        uint32_t b0, uint32_t b1) {
    asm volatile("mma.sync.aligned.m16n8k16.row.col.f32.f16.f16.f32 "
                 "{%0,%1,%2,%3}, {%4,%5,%6,%7}, {%8,%9}, {%0,%1,%2,%3};"
                 : "+f"(c[0]), "+f"(c[1]), "+f"(c[2]), "+f"(c[3])
                 : "r"(a[0]), "r"(a[1]), "r"(a[2]), "r"(a[3]), "r"(b0), "r"(b1));
}
__device__ __forceinline__ uint32_t pack2h(fp16 x, fp16 y) {
    __half2 v = __halves2half2(x, y);
    return *reinterpret_cast<uint32_t*>(&v);
}
__device__ __forceinline__ void split_pack(float v0, float v1, uint32_t& hi, uint32_t& lo) {
    fp16 h0 = __float2half_rn(v0), h1 = __float2half_rn(v1);
    fp16 l0 = __float2half_rn(v0 - __half2float(h0));
    fp16 l1 = __float2half_rn(v1 - __half2float(h1));
    hi = pack2h(h0, h1);
    lo = pack2h(l0, l1);
}

// ---------------------------------------------------------------------------
// split fp32 -> fp16 hi/lo ; convert fp32 -> fp16
// ---------------------------------------------------------------------------
__global__ __launch_bounds__(256) void split_kernel(
    const float* __restrict__ in, fp16* __restrict__ hi, fp16* __restrict__ lo, int n4)
{
    const int i = blockIdx.x * blockDim.x + threadIdx.x;
    if (i >= n4) return;
    float4 v = reinterpret_cast<const float4*>(in)[i];
    uint32_t h0, l0, h1, l1;
    split_pack(v.x, v.y, h0, l0);
    split_pack(v.z, v.w, h1, l1);
    reinterpret_cast<uint2*>(hi)[i] = make_uint2(h0, h1);
    reinterpret_cast<uint2*>(lo)[i] = make_uint2(l0, l1);
}

__global__ __launch_bounds__(256) void cvt_kernel(
    const float* __restrict__ in, fp16* __restrict__ out, int n4)
{
    const int i = blockIdx.x * blockDim.x + threadIdx.x;
    if (i >= n4) return;
    float4 v = reinterpret_cast<const float4*>(in)[i];
    uint32_t h0 = pack2h(__float2half_rn(v.x), __float2half_rn(v.y));
    uint32_t h1 = pack2h(__float2half_rn(v.z), __float2half_rn(v.w));
    reinterpret_cast<uint2*>(out)[i] = make_uint2(h0, h1);
}

// ---------------------------------------------------------------------------
// mma GEMM: out[M,N] = (Ah[+Al])[M,K] @ Bh[N,K]^T + bias
// CTA 128x128, kblock 32, 8 warps (4x2), warp tile 32x64.
// nterms: 1 (Ah only) or 2 (Ah+Al).
// mode 0: fp32 out.  mode 1: fp16 hi/lo head-split.  mode 2: fp16 hi head-split.
// ---------------------------------------------------------------------------
constexpr int GSTR = 40;                     // fp16 stride (80 B rows)
constexpr int GT_BYTES = 128 * GSTR * 2;     // 10240
constexpr int GSTAGE = 3 * GT_BYTES;         // Ah, Al, Bh = 30720
constexpr int GEMM_SMEM = 2 * GSTAGE;        // 61440

__global__ __launch_bounds__(256) void mma_gemm(
    const fp16* __restrict__ Ah, const fp16* __restrict__ Al,
    const fp16* __restrict__ Bh, const float* __restrict__ bias,
    float* __restrict__ out32, fp16* __restrict__ oh, fp16* __restrict__ ol,
    int mode, int nterms)
{
    extern __shared__ char smem[];
    const uint32_t sbb = smem_u32(smem);
    const int tid = threadIdx.x, lane = tid & 31, wid = tid >> 5;
    const int wm = wid & 3, wn = wid >> 2;
    const int m0 = blockIdx.y * 128, n0 = blockIdx.x * 128;

    auto g2s = [&](int stage, int kb) {
        const uint32_t st = sbb + stage * GSTAGE;
        const int k0 = kb * 32;
        #pragma unroll
        for (int j = 0; j < 2; j++) {
            const int idx = tid + j * 256;
            const int r = idx >> 2, kc = (idx & 3) * 8;
            const uint32_t so = (uint32_t)((r * GSTR + kc) * 2);
            CP16(st + 0 * GT_BYTES + so, Ah + (size_t)(m0 + r) * Cv + k0 + kc);
            if (nterms == 2)
                CP16(st + 1 * GT_BYTES + so, Al + (size_t)(m0 + r) * Cv + k0 + kc);
            CP16(st + 2 * GT_BYTES + so, Bh + (size_t)(n0 + r) * Cv + k0 + kc);
        }
    };
    auto fad = [&](uint32_t tb, int rb, int cb) -> uint32_t {
        const int r = rb + (lane & 7) + 8 * ((lane >> 3) & 1);
        const int c = cb + 8 * (lane >> 4);
        return tb + (uint32_t)((r * GSTR + c) * 2);
    };

    float acc[2][8][4] = {};
    g2s(0, 0); CPC();
    g2s(1, 1); CPC();

    for (int kb = 0; kb < Cv / 32; kb++) {
        CPW(1); __syncthreads();
        const uint32_t st = sbb + (kb & 1) * GSTAGE;
        #pragma unroll
        for (int ks = 0; ks < 2; ks++) {
            uint32_t ah[2][4], al[2][4], bh4[4][4];
            #pragma unroll
            for (int mt = 0; mt < 2; mt++) {
                ldsm4(ah[mt], fad(st + 0 * GT_BYTES, wm * 32 + mt * 16, ks * 16));
                if (nterms == 2)
                    ldsm4(al[mt], fad(st + 1 * GT_BYTES, wm * 32 + mt * 16, ks * 16));
            }
            #pragma unroll
            for (int g = 0; g < 4; g++)
                ldsm4(bh4[g], fad(st + 2 * GT_BYTES, wn * 64 + g * 16, ks * 16));
            #pragma unroll
            for (int nt = 0; nt < 8; nt++) {
                const int g = nt >> 1, o = nt & 1;
                const uint32_t b0 = bh4[g][o], b1 = bh4[g][o + 2];
                #pragma unroll
                for (int mt = 0; mt < 2; mt++) {
                    mma_f16(acc[mt][nt], ah[mt], b0, b1);
                    if (nterms == 2)
                        mma_f16(acc[mt][nt], al[mt], b0, b1);
                }
            }
        }
        __syncthreads();
        if (kb + 2 < Cv / 32) g2s(kb & 1, kb + 2);
        CPC();
    }

    // epilogue
    #pragma unroll
    for (int mt = 0; mt < 2; mt++) {
        const int mr = m0 + wm * 32 + mt * 16 + (lane >> 2);
        #pragma unroll
        for (int half = 0; half < 2; half++) {
            const int m = mr + half * 8;
            const int bb = m >> 11, t = m & (Tv - 1);
            #pragma unroll
            for (int nt = 0; nt < 8; nt++) {
                const int n = n0 + wn * 64 + nt * 8 + (lane & 3) * 2;
                const float v0 = acc[mt][nt][half * 2 + 0] + bias[n];
                const float v1 = acc[mt][nt][half * 2 + 1] + bias[n + 1];
                if (mode == 0) {
                    *reinterpret_cast<float2*>(out32 + (size_t)m * Cv + n) = make_float2(v0, v1);
                } else {
                    const int h = n >> 6, d = n & 63;
                    const size_t o = (((size_t)(bb * Hn + h)) * Tv + t) * Dv + d;
                    if (mode == 1) {
                        uint32_t hi, lo;
                        split_pack(v0, v1, hi, lo);
                        *reinterpret_cast<uint32_t*>(oh + o) = hi;
                        *reinterpret_cast<uint32_t*>(ol + o) = lo;
                    } else {
                        *reinterpret_cast<uint32_t*>(oh + o) =
                            pack2h(__float2half_rn(v0), __float2half_rn(v1));
                    }
                }
            }
        }
    }
}

// ---------------------------------------------------------------------------
// mma attention: per (b,h), 128 q rows/CTA, 8 warps, 64-row K/V blocks.
// S = (Qh+Ql) Kh^T ; P = exp(S/8) ; O += Ph Vh ; deferred divide.
// ---------------------------------------------------------------------------
constexpr int VSTR = 72;                     // fp16 stride (144 B rows)
constexpr int QT_BYTES = 128 * VSTR * 2;     // 18432
constexpr int KT_BYTES = 64 * VSTR * 2;      // 9216
constexpr int ASTAGE = 2 * KT_BYTES;         // Kh, Vh = 18432
constexpr int ATT_SMEM = 2 * QT_BYTES + 2 * ASTAGE;   // 73728

__global__ __launch_bounds__(256) void mma_attn()
{
    extern __shared__ char smem[];
    const uint32_t sbb = smem_u32(smem);
    const int tid = threadIdx.x, lane = tid & 31, wid = tid >> 5;
    const int bh = blockIdx.y, q0 = blockIdx.x * 128;

    const fp16* qh = g_qh + (size_t)bh * Tv * Dv;
    const fp16* ql = g_ql + (size_t)bh * Tv * Dv;
    const fp16* kh = g_kh + (size_t)bh * Tv * Dv;
    const fp16* vh = g_vh + (size_t)bh * Tv * Dv;

    const uint32_t QH = sbb, QL = sbb + QT_BYTES, ST0 = sbb + 2 * QT_BYTES;

    #pragma unroll
    for (int j = 0; j < 4; j++) {
        const int idx = tid + j * 256;
        const int r = idx >> 3, dc = (idx & 7) * 8;
        const uint32_t so = (uint32_t)((r * VSTR + dc) * 2);
        CP16(QH + so, qh + (size_t)(q0 + r) * Dv + dc);
        CP16(QL + so, ql + (size_t)(q0 + r) * Dv + dc);
    }
    CPC();

    // 1024 cp.async per stage: idx<512 -> K rows 0..63, idx>=512 -> V rows 0..63
    auto g2s = [&](int stage, int blk) {
        const uint32_t st = ST0 + stage * ASTAGE;
        const int s0 = blk * 64;
        #pragma unroll
        for (int j = 0; j < 4; j++) {
            const int idx = tid + j * 256;          // 0..1023
            const int r = (idx >> 3) & 63;
            const int dc = (idx & 7) * 8;
            const uint32_t so = (uint32_t)((r * VSTR + dc) * 2);
            if (idx < 512) CP16(st + so,            kh + (size_t)(s0 + r) * Dv + dc);
            else           CP16(st + KT_BYTES + so, vh + (size_t)(s0 + r) * Dv + dc);
        }
    };
    auto fad = [&](uint32_t tb, int rb, int cb) -> uint32_t {
        const int r = rb + (lane & 7) + 8 * ((lane >> 3) & 1);
        const int c = cb + 8 * (lane >> 4);
        return tb + (uint32_t)((r * VSTR + c) * 2);
    };

    g2s(0, 0); CPC();
    g2s(1, 1); CPC();
    CPW(2); __syncthreads();   // Q ready

    uint32_t qfh[4][4], qfl[4][4];
    #pragma unroll
    for (int ks = 0; ks < 4; ks++) {
        ldsm4(qfh[ks], fad(QH, wid * 16, ks * 16));
        ldsm4(qfl[ks], fad(QL, wid * 16, ks * 16));
    }

    float oacc[8][4] = {};
    float rs0 = 0.f, rs1 = 0.f;

    for (int blk = 0; blk < Tv / 64; blk++) {
        CPW(1); __syncthreads();
        const uint32_t st = ST0 + (blk & 1) * ASTAGE;

        // S = (Qh+Ql) Kh^T
        float sacc[8][4] = {};
        #pragma unroll
        for (int ks = 0; ks < 4; ks++) {
            uint32_t kf[4][4];
            #pragma unroll
            for (int g = 0; g < 4; g++)
                ldsm4(kf[g], fad(st, g * 16, ks * 16));
            #pragma unroll
            for (int nt = 0; nt < 8; nt++) {
                const int g = nt >> 1, o = nt & 1;
                mma_f16(sacc[nt], qfh[ks], kf[g][o], kf[g][o + 2]);
                mma_f16(sacc[nt], qfl[ks], kf[g][o], kf[g][o + 2]);
            }
        }

        // P = exp(S/8) -> hi fragments only (P rounding errors are iid across s)
        uint32_t pah[4][4];
        #pragma unroll
        for (int nt = 0; nt < 8; nt++) {
            const float p0 = __expf(sacc[nt][0] * 0.125f);
            const float p1 = __expf(sacc[nt][1] * 0.125f);
            const float p2 = __expf(sacc[nt][2] * 0.125f);
            const float p3 = __expf(sacc[nt][3] * 0.125f);
            rs0 += p0 + p1;
            rs1 += p2 + p3;
            const int jj = nt >> 1, off = (nt & 1) * 2;
            pah[jj][off]     = pack2h(__float2half_rn(p0), __float2half_rn(p1));
            pah[jj][off + 1] = pack2h(__float2half_rn(p2), __float2half_rn(p3));
        }

        // O += Ph Vh
        #pragma unroll
        for (int ks = 0; ks < 4; ks++) {
            uint32_t vf[4][4];
            #pragma unroll
            for (int g = 0; g < 4; g++)
                ldsm4t(vf[g], fad(st + KT_BYTES, ks * 16, g * 16));
            #pragma unroll
            for (int dt = 0; dt < 8; dt++) {
                const int g = dt >> 1, o = (dt & 1) * 2;
                mma_f16(oacc[dt], pah[ks], vf[g][o], vf[g][o + 1]);
            }
        }

        __syncthreads();
        if (blk + 2 < Tv / 64) g2s(blk & 1, blk + 2);
        CPC();
    }

    rs0 += __shfl_xor_sync(0xffffffffu, rs0, 1);
    rs0 += __shfl_xor_sync(0xffffffffu, rs0, 2);
    rs1 += __shfl_xor_sync(0xffffffffu, rs1, 1);
    rs1 += __shfl_xor_sync(0xffffffffu, rs1, 2);
    const float inv0 = 1.0f / rs0, inv1 = 1.0f / rs1;

    const int b = bh >> 4, h = bh & 15;
    const int t0 = q0 + wid * 16 + (lane >> 2);
    #pragma unroll
    for (int dt = 0; dt < 8; dt++) {
        const int col = h * 64 + dt * 8 + (lane & 3) * 2;
        uint32_t hi, lo;
        split_pack(oacc[dt][0] * inv0, oacc[dt][1] * inv0, hi, lo);
        size_t o = (size_t)(b * Tv + t0) * Cv + col;
        *reinterpret_cast<uint32_t*>(g_yh + o) = hi;
        *reinterpret_cast<uint32_t*>(g_yl + o) = lo;
        split_pack(oacc[dt][2] * inv1, oacc[dt][3] * inv1, hi, lo);
        o = (size_t)(b * Tv + t0 + 8) * Cv + col;
        *reinterpret_cast<uint32_t*>(g_yh + o) = hi;
        *reinterpret_cast<uint32_t*>(g_yl + o) = lo;
    }
}

// ---------------------------------------------------------------------------
extern "C" void kernel_launch(void* const* d_in, const int* in_sizes, int n_in,
                              void* d_out, int out_size)
{
    const float* x  = (const float*)d_in[0];
    const float* Wq = (const float*)d_in[1];
    const float* bq = (const float*)d_in[2];
    const float* Wk = (const float*)d_in[3];
    const float* bk = (const float*)d_in[4];
    const float* Wv = (const float*)d_in[5];
    const float* bv = (const float*)d_in[6];
    const float* Wp = (const float*)d_in[7];
    const float* bp = (const float*)d_in[8];
    float* out = (float*)d_out;

    fp16 *xh, *xl, *wh, *qh, *ql, *kh, *vh, *yh, *yl;
    cudaGetSymbolAddress((void**)&xh, g_xh); cudaGetSymbolAddress((void**)&xl, g_xl);
    cudaGetSymbolAddress((void**)&wh, g_wh);
    cudaGetSymbolAddress((void**)&qh, g_qh); cudaGetSymbolAddress((void**)&ql, g_ql);
    cudaGetSymbolAddress((void**)&kh, g_kh);
    cudaGetSymbolAddress((void**)&vh, g_vh);
    cudaGetSymbolAddress((void**)&yh, g_yh); cudaGetSymbolAddress((void**)&yl, g_yl);

    cudaFuncSetAttribute(mma_gemm, cudaFuncAttributeMaxDynamicSharedMemorySize, GEMM_SMEM);
    cudaFuncSetAttribute(mma_attn, cudaFuncAttributeMaxDynamicSharedMemorySize, ATT_SMEM);

    const size_t WN = (size_t)Cv * Cv;
    const int xs4 = Mv * Cv / 4, ws4 = (int)(WN / 4);

    split_kernel<<<(xs4 + 255) / 256, 256>>>(x, xh, xl, xs4);
    cvt_kernel<<<(ws4 + 255) / 256, 256>>>(Wq, wh + 0 * WN, ws4);
    cvt_kernel<<<(ws4 + 255) / 256, 256>>>(Wk, wh + 1 * WN, ws4);
    cvt_kernel<<<(ws4 + 255) / 256, 256>>>(Wv, wh + 2 * WN, ws4);
    cvt_kernel<<<(ws4 + 255) / 256, 256>>>(Wp, wh + 3 * WN, ws4);

    dim3 gGrid(Cv / 128, Mv / 128);   // (8, 64)
    // Q: 2-term (correlated logit errors don't average out)
    mma_gemm<<<gGrid, 256, GEMM_SMEM>>>(xh, xl, wh + 0 * WN, bq, nullptr, qh, ql, 1, 2);
    // K, V: 1-term (errors iid across sequence -> averaged out by softmax sum)
    mma_gemm<<<gGrid, 256, GEMM_SMEM>>>(xh, nullptr, wh + 1 * WN, bk, nullptr, kh, nullptr, 2, 1);
    mma_gemm<<<gGrid, 256, GEMM_SMEM>>>(xh, nullptr, wh + 2 * WN, bv, nullptr, vh, nullptr, 2, 1);

    dim3 aGrid(Tv / 128, Bv * Hn);    // (16, 64)
    mma_attn<<<aGrid, 256, ATT_SMEM>>>();

    // final projection: 2-term (errors feed straight to output)
    mma_gemm<<<gGrid, 256, GEMM_SMEM>>>(yh, yl, wh + 3 * WN, bp, out, nullptr, nullptr, 0, 2);
}

// round 8
// speedup vs baseline: 10.8563x; 1.1098x over previous
#include <cuda_runtime.h>
#include <cuda_fp16.h>
#include <cstdint>
#include <cstddef>

using fp16 = __half;

constexpr int Bv = 4, Tv = 2048, Cv = 1024, Hn = 16, Dv = 64;
constexpr int Mv = Bv * Tv;   // 8192

// ---------------------------------------------------------------------------
// Scratch (device globals)
// ---------------------------------------------------------------------------
__device__ fp16 g_xh[(size_t)Mv * Cv];
__device__ fp16 g_wh[(size_t)4 * Cv * Cv];
__device__ fp16 g_qh[(size_t)Mv * Cv];
__device__ fp16 g_kh[(size_t)Mv * Cv];
__device__ fp16 g_vh[(size_t)Mv * Cv];
__device__ fp16 g_yh[(size_t)Mv * Cv], g_yl[(size_t)Mv * Cv];

// ---------------------------------------------------------------------------
// Helpers
// ---------------------------------------------------------------------------
__device__ __forceinline__ uint32_t smem_u32(const void* p) {
    uint32_t a;
    asm("{ .reg .u64 t; cvta.to.shared.u64 t, %1; cvt.u32.u64 %0, t; }" : "=r"(a) : "l"(p));
    return a;
}
#define CP16(dst, src) \
    asm volatile("cp.async.cg.shared.global [%0], [%1], 16;" \
                 :: "r"(dst), "l"(__cvta_generic_to_global(src)) : "memory")
#define CPC() asm volatile("cp.async.commit_group;" ::: "memory")
#define CPW(n) asm volatile("cp.async.wait_group %0;" :: "n"(n) : "memory")

__device__ __forceinline__ void ldsm4(uint32_t r[4], uint32_t a) {
    asm volatile("ldmatrix.sync.aligned.m8n8.x4.shared.b16 {%0,%1,%2,%3}, [%4];"
                 : "=r"(r[0]), "=r"(r[1]), "=r"(r[2]), "=r"(r[3]) : "r"(a));
}
__device__ __forceinline__ void ldsm4t(uint32_t r[4], uint32_t a) {
    asm volatile("ldmatrix.sync.aligned.m8n8.x4.trans.shared.b16 {%0,%1,%2,%3}, [%4];"
                 : "=r"(r[0]), "=r"(r[1]), "=r"(r[2]), "=r"(r[3]) : "r"(a));
}
__device__ __forceinline__ void mma_f16(float c[4], const uint32_t a[4],
                                        uint32_t b0, uint32_t b1) {
    asm volatile("mma.sync.aligned.m16n8k16.row.col.f32.f16.f16.f32 "
                 "{%0,%1,%2,%3}, {%4,%5,%6,%7}, {%8,%9}, {%0,%1,%2,%3};"
                 : "+f"(c[0]), "+f"(c[1]), "+f"(c[2]), "+f"(c[3])
                 : "r"(a[0]), "r"(a[1]), "r"(a[2]), "r"(a[3]), "r"(b0), "r"(b1));
}
__device__ __forceinline__ uint32_t pack2h(fp16 x, fp16 y) {
    __half2 v = __halves2half2(x, y);
    return *reinterpret_cast<uint32_t*>(&v);
}
__device__ __forceinline__ void split_pack(float v0, float v1, uint32_t& hi, uint32_t& lo) {
    fp16 h0 = __float2half_rn(v0), h1 = __float2half_rn(v1);
    fp16 l0 = __float2half_rn(v0 - __half2float(h0));
    fp16 l1 = __float2half_rn(v1 - __half2float(h1));
    hi = pack2h(h0, h1);
    lo = pack2h(l0, l1);
}

// ---------------------------------------------------------------------------
// convert fp32 -> fp16 (single src; and 4-way fused for the weights)
// ---------------------------------------------------------------------------
__global__ __launch_bounds__(256) void cvt_kernel(
    const float* __restrict__ in, fp16* __restrict__ out, int n4)
{
    const int i = blockIdx.x * blockDim.x + threadIdx.x;
    if (i >= n4) return;
    float4 v = reinterpret_cast<const float4*>(in)[i];
    uint32_t h0 = pack2h(__float2half_rn(v.x), __float2half_rn(v.y));
    uint32_t h1 = pack2h(__float2half_rn(v.z), __float2half_rn(v.w));
    reinterpret_cast<uint2*>(out)[i] = make_uint2(h0, h1);
}

__global__ __launch_bounds__(256) void cvt4_kernel(
    const float* __restrict__ s0, const float* __restrict__ s1,
    const float* __restrict__ s2, const float* __restrict__ s3,
    fp16* __restrict__ dst, int n4)
{
    const int i = blockIdx.x * blockDim.x + threadIdx.x;
    if (i >= n4) return;
    const float* s = (blockIdx.y == 0) ? s0 : (blockIdx.y == 1) ? s1
                   : (blockIdx.y == 2) ? s2 : s3;
    fp16* d = dst + (size_t)blockIdx.y * (size_t)Cv * Cv;
    float4 v = reinterpret_cast<const float4*>(s)[i];
    uint32_t h0 = pack2h(__float2half_rn(v.x), __float2half_rn(v.y));
    uint32_t h1 = pack2h(__float2half_rn(v.z), __float2half_rn(v.w));
    reinterpret_cast<uint2*>(d)[i] = make_uint2(h0, h1);
}

// ---------------------------------------------------------------------------
// mma GEMM: out[M,N] = (Ah[+Al])[M,K] @ Bh[N,K]^T + bias
// CTA 128x128, kblock 32, 8 warps (4x2), warp tile 32x64.
// nterms: 1 (Ah only) or 2 (Ah+Al).
// mode 0: fp32 out.  mode 2: fp16 hi head-split.
// ---------------------------------------------------------------------------
constexpr int GSTR = 40;                     // fp16 stride (80 B rows)
constexpr int GT_BYTES = 128 * GSTR * 2;     // 10240
constexpr int GSTAGE = 3 * GT_BYTES;         // Ah, Al, Bh = 30720
constexpr int GEMM_SMEM = 2 * GSTAGE;        // 61440

__global__ __launch_bounds__(256) void mma_gemm(
    const fp16* __restrict__ Ah, const fp16* __restrict__ Al,
    const fp16* __restrict__ Bh, const float* __restrict__ bias,
    float* __restrict__ out32, fp16* __restrict__ oh,
    int mode, int nterms)
{
    extern __shared__ char smem[];
    const uint32_t sbb = smem_u32(smem);
    const int tid = threadIdx.x, lane = tid & 31, wid = tid >> 5;
    const int wm = wid & 3, wn = wid >> 2;
    const int m0 = blockIdx.y * 128, n0 = blockIdx.x * 128;

    auto g2s = [&](int stage, int kb) {
        const uint32_t st = sbb + stage * GSTAGE;
        const int k0 = kb * 32;
        #pragma unroll
        for (int j = 0; j < 2; j++) {
            const int idx = tid + j * 256;
            const int r = idx >> 2, kc = (idx & 3) * 8;
            const uint32_t so = (uint32_t)((r * GSTR + kc) * 2);
            CP16(st + 0 * GT_BYTES + so, Ah + (size_t)(m0 + r) * Cv + k0 + kc);
            if (nterms == 2)
                CP16(st + 1 * GT_BYTES + so, Al + (size_t)(m0 + r) * Cv + k0 + kc);
            CP16(st + 2 * GT_BYTES + so, Bh + (size_t)(n0 + r) * Cv + k0 + kc);
        }
    };
    auto fad = [&](uint32_t tb, int rb, int cb) -> uint32_t {
        const int r = rb + (lane & 7) + 8 * ((lane >> 3) & 1);
        const int c = cb + 8 * (lane >> 4);
        return tb + (uint32_t)((r * GSTR + c) * 2);
    };

    float acc[2][8][4] = {};
    g2s(0, 0); CPC();
    g2s(1, 1); CPC();

    for (int kb = 0; kb < Cv / 32; kb++) {
        CPW(1); __syncthreads();
        const uint32_t st = sbb + (kb & 1) * GSTAGE;
        #pragma unroll
        for (int ks = 0; ks < 2; ks++) {
            uint32_t ah[2][4], al[2][4], bh4[4][4];
            #pragma unroll
            for (int mt = 0; mt < 2; mt++) {
                ldsm4(ah[mt], fad(st + 0 * GT_BYTES, wm * 32 + mt * 16, ks * 16));
                if (nterms == 2)
                    ldsm4(al[mt], fad(st + 1 * GT_BYTES, wm * 32 + mt * 16, ks * 16));
            }
            #pragma unroll
            for (int g = 0; g < 4; g++)
                ldsm4(bh4[g], fad(st + 2 * GT_BYTES, wn * 64 + g * 16, ks * 16));
            #pragma unroll
            for (int nt = 0; nt < 8; nt++) {
                const int g = nt >> 1, o = nt & 1;
                const uint32_t b0 = bh4[g][o], b1 = bh4[g][o + 2];
                #pragma unroll
                for (int mt = 0; mt < 2; mt++) {
                    mma_f16(acc[mt][nt], ah[mt], b0, b1);
                    if (nterms == 2)
                        mma_f16(acc[mt][nt], al[mt], b0, b1);
                }
            }
        }
        __syncthreads();
        if (kb + 2 < Cv / 32) g2s(kb & 1, kb + 2);
        CPC();
    }

    // epilogue
    #pragma unroll
    for (int mt = 0; mt < 2; mt++) {
        const int mr = m0 + wm * 32 + mt * 16 + (lane >> 2);
        #pragma unroll
        for (int half = 0; half < 2; half++) {
            const int m = mr + half * 8;
            const int bb = m >> 11, t = m & (Tv - 1);
            #pragma unroll
            for (int nt = 0; nt < 8; nt++) {
                const int n = n0 + wn * 64 + nt * 8 + (lane & 3) * 2;
                const float v0 = acc[mt][nt][half * 2 + 0] + bias[n];
                const float v1 = acc[mt][nt][half * 2 + 1] + bias[n + 1];
                if (mode == 0) {
                    *reinterpret_cast<float2*>(out32 + (size_t)m * Cv + n) = make_float2(v0, v1);
                } else {
                    const int h = n >> 6, d = n & 63;
                    const size_t o = (((size_t)(bb * Hn + h)) * Tv + t) * Dv + d;
                    *reinterpret_cast<uint32_t*>(oh + o) =
                        pack2h(__float2half_rn(v0), __float2half_rn(v1));
                }
            }
        }
    }
}

// ---------------------------------------------------------------------------
// mma attention: per (b,h), 128 q rows/CTA, 8 warps, 64-row K/V blocks.
// S = Qh Kh^T ; P = exp(S/8) ; O += Ph Vh ; deferred divide; y out as hi/lo.
// ---------------------------------------------------------------------------
constexpr int VSTR = 72;                     // fp16 stride (144 B rows)
constexpr int QT_BYTES = 128 * VSTR * 2;     // 18432
constexpr int KT_BYTES = 64 * VSTR * 2;      // 9216
constexpr int ASTAGE = 2 * KT_BYTES;         // Kh, Vh = 18432
constexpr int ATT_SMEM = QT_BYTES + 2 * ASTAGE;   // 55296

__global__ __launch_bounds__(256) void mma_attn()
{
    extern __shared__ char smem[];
    const uint32_t sbb = smem_u32(smem);
    const int tid = threadIdx.x, lane = tid & 31, wid = tid >> 5;
    const int bh = blockIdx.y, q0 = blockIdx.x * 128;

    const fp16* qh = g_qh + (size_t)bh * Tv * Dv;
    const fp16* kh = g_kh + (size_t)bh * Tv * Dv;
    const fp16* vh = g_vh + (size_t)bh * Tv * Dv;

    const uint32_t QH = sbb, ST0 = sbb + QT_BYTES;

    // Q tile (128x64): 1024 cp.async
    #pragma unroll
    for (int j = 0; j < 4; j++) {
        const int idx = tid + j * 256;
        const int r = idx >> 3, dc = (idx & 7) * 8;
        const uint32_t so = (uint32_t)((r * VSTR + dc) * 2);
        CP16(QH + so, qh + (size_t)(q0 + r) * Dv + dc);
    }
    CPC();

    // 1024 cp.async per stage: idx<512 -> K rows 0..63, idx>=512 -> V rows 0..63
    auto g2s = [&](int stage, int blk) {
        const uint32_t st = ST0 + stage * ASTAGE;
        const int s0 = blk * 64;
        #pragma unroll
        for (int j = 0; j < 4; j++) {
            const int idx = tid + j * 256;          // 0..1023
            const int r = (idx >> 3) & 63;
            const int dc = (idx & 7) * 8;
            const uint32_t so = (uint32_t)((r * VSTR + dc) * 2);
            if (idx < 512) CP16(st + so,            kh + (size_t)(s0 + r) * Dv + dc);
            else           CP16(st + KT_BYTES + so, vh + (size_t)(s0 + r) * Dv + dc);
        }
    };
    auto fad = [&](uint32_t tb, int rb, int cb) -> uint32_t {
        const int r = rb + (lane & 7) + 8 * ((lane >> 3) & 1);
        const int c = cb + 8 * (lane >> 4);
        return tb + (uint32_t)((r * VSTR + c) * 2);
    };

    g2s(0, 0); CPC();
    g2s(1, 1); CPC();
    CPW(2); __syncthreads();   // Q ready

    uint32_t qfh[4][4];
    #pragma unroll
    for (int ks = 0; ks < 4; ks++)
        ldsm4(qfh[ks], fad(QH, wid * 16, ks * 16));

    float oacc[8][4] = {};
    float rs0 = 0.f, rs1 = 0.f;

    for (int blk = 0; blk < Tv / 64; blk++) {
        CPW(1); __syncthreads();
        const uint32_t st = ST0 + (blk & 1) * ASTAGE;

        // S = Qh Kh^T
        float sacc[8][4] = {};
        #pragma unroll
        for (int ks = 0; ks < 4; ks++) {
            uint32_t kf[4][4];
            #pragma unroll
            for (int g = 0; g < 4; g++)
                ldsm4(kf[g], fad(st, g * 16, ks * 16));
            #pragma unroll
            for (int nt = 0; nt < 8; nt++) {
                const int g = nt >> 1, o = nt & 1;
                mma_f16(sacc[nt], qfh[ks], kf[g][o], kf[g][o + 2]);
            }
        }

        // P = exp(S/8) -> hi fragments only
        uint32_t pah[4][4];
        #pragma unroll
        for (int nt = 0; nt < 8; nt++) {
            const float p0 = __expf(sacc[nt][0] * 0.125f);
            const float p1 = __expf(sacc[nt][1] * 0.125f);
            const float p2 = __expf(sacc[nt][2] * 0.125f);
            const float p3 = __expf(sacc[nt][3] * 0.125f);
            rs0 += p0 + p1;
            rs1 += p2 + p3;
            const int jj = nt >> 1, off = (nt & 1) * 2;
            pah[jj][off]     = pack2h(__float2half_rn(p0), __float2half_rn(p1));
            pah[jj][off + 1] = pack2h(__float2half_rn(p2), __float2half_rn(p3));
        }

        // O += Ph Vh
        #pragma unroll
        for (int ks = 0; ks < 4; ks++) {
            uint32_t vf[4][4];
            #pragma unroll
            for (int g = 0; g < 4; g++)
                ldsm4t(vf[g], fad(st + KT_BYTES, ks * 16, g * 16));
            #pragma unroll
            for (int dt = 0; dt < 8; dt++) {
                const int g = dt >> 1, o = (dt & 1) * 2;
                mma_f16(oacc[dt], pah[ks], vf[g][o], vf[g][o + 1]);
            }
        }

        __syncthreads();
        if (blk + 2 < Tv / 64) g2s(blk & 1, blk + 2);
        CPC();
    }

    rs0 += __shfl_xor_sync(0xffffffffu, rs0, 1);
    rs0 += __shfl_xor_sync(0xffffffffu, rs0, 2);
    rs1 += __shfl_xor_sync(0xffffffffu, rs1, 1);
    rs1 += __shfl_xor_sync(0xffffffffu, rs1, 2);
    const float inv0 = 1.0f / rs0, inv1 = 1.0f / rs1;

    const int b = bh >> 4, h = bh & 15;
    const int t0 = q0 + wid * 16 + (lane >> 2);
    #pragma unroll
    for (int dt = 0; dt < 8; dt++) {
        const int col = h * 64 + dt * 8 + (lane & 3) * 2;
        uint32_t hi, lo;
        split_pack(oacc[dt][0] * inv0, oacc[dt][1] * inv0, hi, lo);
        size_t o = (size_t)(b * Tv + t0) * Cv + col;
        *reinterpret_cast<uint32_t*>(g_yh + o) = hi;
        *reinterpret_cast<uint32_t*>(g_yl + o) = lo;
        split_pack(oacc[dt][2] * inv1, oacc[dt][3] * inv1, hi, lo);
        o = (size_t)(b * Tv + t0 + 8) * Cv + col;
        *reinterpret_cast<uint32_t*>(g_yh + o) = hi;
        *reinterpret_cast<uint32_t*>(g_yl + o) = lo;
    }
}

// ---------------------------------------------------------------------------
extern "C" void kernel_launch(void* const* d_in, const int* in_sizes, int n_in,
                              void* d_out, int out_size)
{
    const float* x  = (const float*)d_in[0];
    const float* Wq = (const float*)d_in[1];
    const float* bq = (const float*)d_in[2];
    const float* Wk = (const float*)d_in[3];
    const float* bk = (const float*)d_in[4];
    const float* Wv = (const float*)d_in[5];
    const float* bv = (const float*)d_in[6];
    const float* Wp = (const float*)d_in[7];
    const float* bp = (const float*)d_in[8];
    float* out = (float*)d_out;

    fp16 *xh, *wh, *qh, *kh, *vh, *yh, *yl;
    cudaGetSymbolAddress((void**)&xh, g_xh);
    cudaGetSymbolAddress((void**)&wh, g_wh);
    cudaGetSymbolAddress((void**)&qh, g_qh);
    cudaGetSymbolAddress((void**)&kh, g_kh);
    cudaGetSymbolAddress((void**)&vh, g_vh);
    cudaGetSymbolAddress((void**)&yh, g_yh);
    cudaGetSymbolAddress((void**)&yl, g_yl);

    cudaFuncSetAttribute(mma_gemm, cudaFuncAttributeMaxDynamicSharedMemorySize, GEMM_SMEM);
    cudaFuncSetAttribute(mma_attn, cudaFuncAttributeMaxDynamicSharedMemorySize, ATT_SMEM);

    const size_t WN = (size_t)Cv * Cv;
    const int xs4 = Mv * Cv / 4, ws4 = (int)(WN / 4);

    cvt_kernel<<<(xs4 + 255) / 256, 256>>>(x, xh, xs4);
    {
        dim3 cg((ws4 + 255) / 256, 4);
        cvt4_kernel<<<cg, 256>>>(Wq, Wk, Wv, Wp, wh, ws4);
    }

    dim3 gGrid(Cv / 128, Mv / 128);   // (8, 64)
    // Q, K, V projections: 1-term (downstream softmax averaging kills the residuals)
    mma_gemm<<<gGrid, 256, GEMM_SMEM>>>(xh, nullptr, wh + 0 * WN, bq, nullptr, qh, 2, 1);
    mma_gemm<<<gGrid, 256, GEMM_SMEM>>>(xh, nullptr, wh + 1 * WN, bk, nullptr, kh, 2, 1);
    mma_gemm<<<gGrid, 256, GEMM_SMEM>>>(xh, nullptr, wh + 2 * WN, bv, nullptr, vh, 2, 1);

    dim3 aGrid(Tv / 128, Bv * Hn);    // (16, 64)
    mma_attn<<<aGrid, 256, ATT_SMEM>>>();

    // final projection: 2-term y (errors feed straight to output)
    mma_gemm<<<gGrid, 256, GEMM_SMEM>>>(yh, yl, wh + 3 * WN, bp, out, nullptr, 0, 2);
}

// round 9
// speedup vs baseline: 12.8039x; 1.1794x over previous
#include <cuda_runtime.h>
#include <cuda_fp16.h>
#include <cstdint>
#include <cstddef>

using fp16 = __half;

constexpr int Bv = 4, Tv = 2048, Cv = 1024, Hn = 16, Dv = 64;
constexpr int Mv = Bv * Tv;   // 8192

// ---------------------------------------------------------------------------
// Scratch (device globals)
// ---------------------------------------------------------------------------
__device__ fp16 g_xh[(size_t)Mv * Cv];
__device__ fp16 g_wh[(size_t)4 * Cv * Cv];
__device__ fp16 g_qh[(size_t)Mv * Cv];
__device__ fp16 g_kh[(size_t)Mv * Cv];
__device__ fp16 g_vh[(size_t)Mv * Cv];
__device__ fp16 g_yh[(size_t)Mv * Cv], g_yl[(size_t)Mv * Cv];

// ---------------------------------------------------------------------------
// Helpers
// ---------------------------------------------------------------------------
__device__ __forceinline__ uint32_t smem_u32(const void* p) {
    uint32_t a;
    asm("{ .reg .u64 t; cvta.to.shared.u64 t, %1; cvt.u32.u64 %0, t; }" : "=r"(a) : "l"(p));
    return a;
}
#define CP16(dst, src) \
    asm volatile("cp.async.cg.shared.global [%0], [%1], 16;" \
                 :: "r"(dst), "l"(__cvta_generic_to_global(src)) : "memory")
#define CPC() asm volatile("cp.async.commit_group;" ::: "memory")
#define CPW(n) asm volatile("cp.async.wait_group %0;" :: "n"(n) : "memory")

__device__ __forceinline__ void ldsm4(uint32_t r[4], uint32_t a) {
    asm volatile("ldmatrix.sync.aligned.m8n8.x4.shared.b16 {%0,%1,%2,%3}, [%4];"
                 : "=r"(r[0]), "=r"(r[1]), "=r"(r[2]), "=r"(r[3]) : "r"(a));
}
__device__ __forceinline__ void ldsm4t(uint32_t r[4], uint32_t a) {
    asm volatile("ldmatrix.sync.aligned.m8n8.x4.trans.shared.b16 {%0,%1,%2,%3}, [%4];"
                 : "=r"(r[0]), "=r"(r[1]), "=r"(r[2]), "=r"(r[3]) : "r"(a));
}
__device__ __forceinline__ void mma_f16(float c[4], const uint32_t a[4],
                                        uint32_t b0, uint32_t b1) {
    asm volatile("mma.sync.aligned.m16n8k16.row.col.f32.f16.f16.f32 "
                 "{%0,%1,%2,%3}, {%4,%5,%6,%7}, {%8,%9}, {%0,%1,%2,%3};"
                 : "+f"(c[0]), "+f"(c[1]), "+f"(c[2]), "+f"(c[3])
                 : "r"(a[0]), "r"(a[1]), "r"(a[2]), "r"(a[3]), "r"(b0), "r"(b1));
}
__device__ __forceinline__ uint32_t pack2h(fp16 x, fp16 y) {
    __half2 v = __halves2half2(x, y);
    return *reinterpret_cast<uint32_t*>(&v);
}
__device__ __forceinline__ void split_pack(float v0, float v1, uint32_t& hi, uint32_t& lo) {
    fp16 h0 = __float2half_rn(v0), h1 = __float2half_rn(v1);
    fp16 l0 = __float2half_rn(v0 - __half2float(h0));
    fp16 l1 = __float2half_rn(v1 - __half2float(h1));
    hi = pack2h(h0, h1);
    lo = pack2h(l0, l1);
}

// ---------------------------------------------------------------------------
// converts
// ---------------------------------------------------------------------------
__global__ __launch_bounds__(256) void cvt_kernel(
    const float* __restrict__ in, fp16* __restrict__ out, int n4)
{
    const int i = blockIdx.x * blockDim.x + threadIdx.x;
    if (i >= n4) return;
    float4 v = reinterpret_cast<const float4*>(in)[i];
    uint32_t h0 = pack2h(__float2half_rn(v.x), __float2half_rn(v.y));
    uint32_t h1 = pack2h(__float2half_rn(v.z), __float2half_rn(v.w));
    reinterpret_cast<uint2*>(out)[i] = make_uint2(h0, h1);
}

__global__ __launch_bounds__(256) void cvt4_kernel(
    const float* __restrict__ s0, const float* __restrict__ s1,
    const float* __restrict__ s2, const float* __restrict__ s3,
    fp16* __restrict__ dst, int n4)
{
    const int i = blockIdx.x * blockDim.x + threadIdx.x;
    if (i >= n4) return;
    const float* s = (blockIdx.y == 0) ? s0 : (blockIdx.y == 1) ? s1
                   : (blockIdx.y == 2) ? s2 : s3;
    fp16* d = dst + (size_t)blockIdx.y * (size_t)Cv * Cv;
    float4 v = reinterpret_cast<const float4*>(s)[i];
    uint32_t h0 = pack2h(__float2half_rn(v.x), __float2half_rn(v.y));
    uint32_t h1 = pack2h(__float2half_rn(v.z), __float2half_rn(v.w));
    reinterpret_cast<uint2*>(d)[i] = make_uint2(h0, h1);
}

// ---------------------------------------------------------------------------
// mma GEMM (templated): out[M,N] = (Ah[+Al])[M,K] @ Bh[N,K]^T + bias
// CTA 128x128, kblock 32, 8 warps (4x2), warp tile 32x64.
// NTERMS in {1,2}. MODE 0: fp32 out. MODE 2: fp16 head-split hi out.
// Multi-stage cp.async pipeline, loads issued before compute each iter.
// ---------------------------------------------------------------------------
constexpr int GSTR = 40;                     // fp16 stride (80 B rows)
constexpr int GT_BYTES = 128 * GSTR * 2;     // 10240
constexpr int NKB = Cv / 32;                 // 32

template <int NTERMS, int MODE>
__global__ __launch_bounds__(256) void mma_gemm(
    const fp16* __restrict__ Ah, const fp16* __restrict__ Al,
    const fp16* __restrict__ Bh, const float* __restrict__ bias,
    float* __restrict__ out32, fp16* __restrict__ oh)
{
    constexpr int STAGE = (NTERMS + 1) * GT_BYTES;
    constexpr int S = (NTERMS == 1) ? 4 : 3;

    extern __shared__ char smem[];
    const uint32_t sbb = smem_u32(smem);
    const int tid = threadIdx.x, lane = tid & 31, wid = tid >> 5;
    const int wm = wid & 3, wn = wid >> 2;
    const int m0 = blockIdx.y * 128, n0 = blockIdx.x * 128;

    auto g2s = [&](int stage, int kb) {
        const uint32_t st = sbb + stage * STAGE;
        const int k0 = kb * 32;
        #pragma unroll
        for (int j = 0; j < 2; j++) {
            const int idx = tid + j * 256;
            const int r = idx >> 2, kc = (idx & 3) * 8;
            const uint32_t so = (uint32_t)((r * GSTR + kc) * 2);
            CP16(st + 0 * GT_BYTES + so, Ah + (size_t)(m0 + r) * Cv + k0 + kc);
            if (NTERMS == 2)
                CP16(st + 1 * GT_BYTES + so, Al + (size_t)(m0 + r) * Cv + k0 + kc);
            CP16(st + NTERMS * GT_BYTES + so, Bh + (size_t)(n0 + r) * Cv + k0 + kc);
        }
    };
    auto fad = [&](uint32_t tb, int rb, int cb) -> uint32_t {
        const int r = rb + (lane & 7) + 8 * ((lane >> 3) & 1);
        const int c = cb + 8 * (lane >> 4);
        return tb + (uint32_t)((r * GSTR + c) * 2);
    };

    float acc[2][8][4] = {};

    #pragma unroll
    for (int s = 0; s < S - 1; s++) { g2s(s, s); CPC(); }

    for (int kb = 0; kb < NKB; kb++) {
        CPW(S - 2);
        __syncthreads();
        // early prefetch into the stage freed at iteration kb-1
        if (kb + S - 1 < NKB) g2s((kb + S - 1) % S, kb + S - 1);
        CPC();

        const uint32_t st = sbb + (kb % S) * STAGE;
        #pragma unroll
        for (int ks = 0; ks < 2; ks++) {
            uint32_t ah[2][4], al[2][4], bh4[4][4];
            #pragma unroll
            for (int mt = 0; mt < 2; mt++) {
                ldsm4(ah[mt], fad(st + 0 * GT_BYTES, wm * 32 + mt * 16, ks * 16));
                if (NTERMS == 2)
                    ldsm4(al[mt], fad(st + 1 * GT_BYTES, wm * 32 + mt * 16, ks * 16));
            }
            #pragma unroll
            for (int g = 0; g < 4; g++)
                ldsm4(bh4[g], fad(st + NTERMS * GT_BYTES, wn * 64 + g * 16, ks * 16));
            #pragma unroll
            for (int nt = 0; nt < 8; nt++) {
                const int g = nt >> 1, o = nt & 1;
                const uint32_t b0 = bh4[g][o], b1 = bh4[g][o + 2];
                #pragma unroll
                for (int mt = 0; mt < 2; mt++) {
                    mma_f16(acc[mt][nt], ah[mt], b0, b1);
                    if (NTERMS == 2)
                        mma_f16(acc[mt][nt], al[mt], b0, b1);
                }
            }
        }
    }

    // epilogue
    #pragma unroll
    for (int mt = 0; mt < 2; mt++) {
        const int mr = m0 + wm * 32 + mt * 16 + (lane >> 2);
        #pragma unroll
        for (int half = 0; half < 2; half++) {
            const int m = mr + half * 8;
            const int bb = m >> 11, t = m & (Tv - 1);
            #pragma unroll
            for (int nt = 0; nt < 8; nt++) {
                const int n = n0 + wn * 64 + nt * 8 + (lane & 3) * 2;
                const float v0 = acc[mt][nt][half * 2 + 0] + bias[n];
                const float v1 = acc[mt][nt][half * 2 + 1] + bias[n + 1];
                if (MODE == 0) {
                    *reinterpret_cast<float2*>(out32 + (size_t)m * Cv + n) = make_float2(v0, v1);
                } else {
                    const int h = n >> 6, d = n & 63;
                    const size_t o = (((size_t)(bb * Hn + h)) * Tv + t) * Dv + d;
                    *reinterpret_cast<uint32_t*>(oh + o) =
                        pack2h(__float2half_rn(v0), __float2half_rn(v1));
                }
            }
        }
    }
}

// ---------------------------------------------------------------------------
// mma attention: per (b,h), 128 q rows/CTA, 8 warps, 64-row K/V blocks.
// 4-stage cp.async pipeline; S = Qh Kh^T ; P = exp(S/8) ; O += Ph Vh.
// ---------------------------------------------------------------------------
constexpr int VSTR = 72;                     // fp16 stride (144 B rows)
constexpr int QT_BYTES = 128 * VSTR * 2;     // 18432
constexpr int KT_BYTES = 64 * VSTR * 2;      // 9216
constexpr int ASTAGE = 2 * KT_BYTES;         // Kh, Vh = 18432
constexpr int AS_N = 4;                      // stages
constexpr int ATT_SMEM = QT_BYTES + AS_N * ASTAGE;   // 92160
constexpr int NBLK = Tv / 64;                // 32

__global__ __launch_bounds__(256) void mma_attn()
{
    extern __shared__ char smem[];
    const uint32_t sbb = smem_u32(smem);
    const int tid = threadIdx.x, lane = tid & 31, wid = tid >> 5;
    const int bh = blockIdx.y, q0 = blockIdx.x * 128;

    const fp16* qh = g_qh + (size_t)bh * Tv * Dv;
    const fp16* kh = g_kh + (size_t)bh * Tv * Dv;
    const fp16* vh = g_vh + (size_t)bh * Tv * Dv;

    const uint32_t QH = sbb, ST0 = sbb + QT_BYTES;

    auto g2s = [&](int stage, int blk) {
        const uint32_t st = ST0 + stage * ASTAGE;
        const int s0 = blk * 64;
        #pragma unroll
        for (int j = 0; j < 4; j++) {
            const int idx = tid + j * 256;          // 0..1023
            const int r = (idx >> 3) & 63;
            const int dc = (idx & 7) * 8;
            const uint32_t so = (uint32_t)((r * VSTR + dc) * 2);
            if (idx < 512) CP16(st + so,            kh + (size_t)(s0 + r) * Dv + dc);
            else           CP16(st + KT_BYTES + so, vh + (size_t)(s0 + r) * Dv + dc);
        }
    };
    auto fad = [&](uint32_t tb, int rb, int cb) -> uint32_t {
        const int r = rb + (lane & 7) + 8 * ((lane >> 3) & 1);
        const int c = cb + 8 * (lane >> 4);
        return tb + (uint32_t)((r * VSTR + c) * 2);
    };

    // prologue: group0 = Q + stage0, then stage1, stage2
    #pragma unroll
    for (int j = 0; j < 4; j++) {
        const int idx = tid + j * 256;
        const int r = idx >> 3, dc = (idx & 7) * 8;
        const uint32_t so = (uint32_t)((r * VSTR + dc) * 2);
        CP16(QH + so, qh + (size_t)(q0 + r) * Dv + dc);
    }
    g2s(0, 0); CPC();
    g2s(1, 1); CPC();
    g2s(2, 2); CPC();

    // wait for group0 (Q + stage0), load Q fragments
    CPW(2); __syncthreads();
    uint32_t qfh[4][4];
    #pragma unroll
    for (int ks = 0; ks < 4; ks++)
        ldsm4(qfh[ks], fad(QH, wid * 16, ks * 16));

    float oacc[8][4] = {};
    float rs0 = 0.f, rs1 = 0.f;

    for (int blk = 0; blk < NBLK; blk++) {
        CPW(2);
        __syncthreads();
        if (blk + 3 < NBLK) g2s((blk + 3) % AS_N, blk + 3);
        CPC();

        const uint32_t st = ST0 + (blk % AS_N) * ASTAGE;

        // S = Qh Kh^T
        float sacc[8][4] = {};
        #pragma unroll
        for (int ks = 0; ks < 4; ks++) {
            uint32_t kf[4][4];
            #pragma unroll
            for (int g = 0; g < 4; g++)
                ldsm4(kf[g], fad(st, g * 16, ks * 16));
            #pragma unroll
            for (int nt = 0; nt < 8; nt++) {
                const int g = nt >> 1, o = nt & 1;
                mma_f16(sacc[nt], qfh[ks], kf[g][o], kf[g][o + 2]);
            }
        }

        // P = exp(S/8)
        uint32_t pah[4][4];
        #pragma unroll
        for (int nt = 0; nt < 8; nt++) {
            const float p0 = __expf(sacc[nt][0] * 0.125f);
            const float p1 = __expf(sacc[nt][1] * 0.125f);
            const float p2 = __expf(sacc[nt][2] * 0.125f);
            const float p3 = __expf(sacc[nt][3] * 0.125f);
            rs0 += p0 + p1;
            rs1 += p2 + p3;
            const int jj = nt >> 1, off = (nt & 1) * 2;
            pah[jj][off]     = pack2h(__float2half_rn(p0), __float2half_rn(p1));
            pah[jj][off + 1] = pack2h(__float2half_rn(p2), __float2half_rn(p3));
        }

        // O += Ph Vh
        #pragma unroll
        for (int ks = 0; ks < 4; ks++) {
            uint32_t vf[4][4];
            #pragma unroll
            for (int g = 0; g < 4; g++)
                ldsm4t(vf[g], fad(st + KT_BYTES, ks * 16, g * 16));
            #pragma unroll
            for (int dt = 0; dt < 8; dt++) {
                const int g = dt >> 1, o = (dt & 1) * 2;
                mma_f16(oacc[dt], pah[ks], vf[g][o], vf[g][o + 1]);
            }
        }
    }

    rs0 += __shfl_xor_sync(0xffffffffu, rs0, 1);
    rs0 += __shfl_xor_sync(0xffffffffu, rs0, 2);
    rs1 += __shfl_xor_sync(0xffffffffu, rs1, 1);
    rs1 += __shfl_xor_sync(0xffffffffu, rs1, 2);
    const float inv0 = 1.0f / rs0, inv1 = 1.0f / rs1;

    const int b = bh >> 4, h = bh & 15;
    const int t0 = q0 + wid * 16 + (lane >> 2);
    #pragma unroll
    for (int dt = 0; dt < 8; dt++) {
        const int col = h * 64 + dt * 8 + (lane & 3) * 2;
        uint32_t hi, lo;
        split_pack(oacc[dt][0] * inv0, oacc[dt][1] * inv0, hi, lo);
        size_t o = (size_t)(b * Tv + t0) * Cv + col;
        *reinterpret_cast<uint32_t*>(g_yh + o) = hi;
        *reinterpret_cast<uint32_t*>(g_yl + o) = lo;
        split_pack(oacc[dt][2] * inv1, oacc[dt][3] * inv1, hi, lo);
        o = (size_t)(b * Tv + t0 + 8) * Cv + col;
        *reinterpret_cast<uint32_t*>(g_yh + o) = hi;
        *reinterpret_cast<uint32_t*>(g_yl + o) = lo;
    }
}

// ---------------------------------------------------------------------------
extern "C" void kernel_launch(void* const* d_in, const int* in_sizes, int n_in,
                              void* d_out, int out_size)
{
    const float* x  = (const float*)d_in[0];
    const float* Wq = (const float*)d_in[1];
    const float* bq = (const float*)d_in[2];
    const float* Wk = (const float*)d_in[3];
    const float* bk = (const float*)d_in[4];
    const float* Wv = (const float*)d_in[5];
    const float* bv = (const float*)d_in[6];
    const float* Wp = (const float*)d_in[7];
    const float* bp = (const float*)d_in[8];
    float* out = (float*)d_out;

    fp16 *xh, *wh, *qh, *kh, *vh, *yh, *yl;
    cudaGetSymbolAddress((void**)&xh, g_xh);
    cudaGetSymbolAddress((void**)&wh, g_wh);
    cudaGetSymbolAddress((void**)&qh, g_qh);
    cudaGetSymbolAddress((void**)&kh, g_kh);
    cudaGetSymbolAddress((void**)&vh, g_vh);
    cudaGetSymbolAddress((void**)&yh, g_yh);
    cudaGetSymbolAddress((void**)&yl, g_yl);

    constexpr int SM1 = 4 * 2 * GT_BYTES;    // 81920 (1-term, 4 stages)
    constexpr int SM2 = 3 * 3 * GT_BYTES;    // 92160 (2-term, 3 stages)
    cudaFuncSetAttribute(mma_gemm<1, 2>, cudaFuncAttributeMaxDynamicSharedMemorySize, SM1);
    cudaFuncSetAttribute(mma_gemm<2, 0>, cudaFuncAttributeMaxDynamicSharedMemorySize, SM2);
    cudaFuncSetAttribute(mma_attn, cudaFuncAttributeMaxDynamicSharedMemorySize, ATT_SMEM);

    const size_t WN = (size_t)Cv * Cv;
    const int xs4 = Mv * Cv / 4, ws4 = (int)(WN / 4);

    cvt_kernel<<<(xs4 + 255) / 256, 256>>>(x, xh, xs4);
    {
        dim3 cg((ws4 + 255) / 256, 4);
        cvt4_kernel<<<cg, 256>>>(Wq, Wk, Wv, Wp, wh, ws4);
    }

    dim3 gGrid(Cv / 128, Mv / 128);   // (8, 64)
    mma_gemm<1, 2><<<gGrid, 256, SM1>>>(xh, nullptr, wh + 0 * WN, bq, nullptr, qh);
    mma_gemm<1, 2><<<gGrid, 256, SM1>>>(xh, nullptr, wh + 1 * WN, bk, nullptr, kh);
    mma_gemm<1, 2><<<gGrid, 256, SM1>>>(xh, nullptr, wh + 2 * WN, bv, nullptr, vh);

    dim3 aGrid(Tv / 128, Bv * Hn);    // (16, 64)
    mma_attn<<<aGrid, 256, ATT_SMEM>>>();

    mma_gemm<2, 0><<<gGrid, 256, SM2>>>(yh, yl, wh + 3 * WN, bp, out, nullptr);
}

// round 10
// speedup vs baseline: 14.1091x; 1.1019x over previous
#include <cuda_runtime.h>
#include <cuda_fp16.h>
#include <cstdint>
#include <cstddef>

using fp16 = __half;

constexpr int Bv = 4, Tv = 2048, Cv = 1024, Hn = 16, Dv = 64;
constexpr int Mv = Bv * Tv;   // 8192

// ---------------------------------------------------------------------------
// Scratch (device globals)
// ---------------------------------------------------------------------------
__device__ fp16 g_xh[(size_t)Mv * Cv];
__device__ fp16 g_wh[(size_t)4 * Cv * Cv];
__device__ fp16 g_qh[(size_t)Mv * Cv];
__device__ fp16 g_kh[(size_t)Mv * Cv];
__device__ fp16 g_vh[(size_t)Mv * Cv];
__device__ fp16 g_yh[(size_t)Mv * Cv], g_yl[(size_t)Mv * Cv];

// ---------------------------------------------------------------------------
// Helpers
// ---------------------------------------------------------------------------
__device__ __forceinline__ uint32_t smem_u32(const void* p) {
    uint32_t a;
    asm("{ .reg .u64 t; cvta.to.shared.u64 t, %1; cvt.u32.u64 %0, t; }" : "=r"(a) : "l"(p));
    return a;
}
#define CP16(dst, src) \
    asm volatile("cp.async.cg.shared.global [%0], [%1], 16;" \
                 :: "r"(dst), "l"(__cvta_generic_to_global(src)) : "memory")
#define CPC() asm volatile("cp.async.commit_group;" ::: "memory")
#define CPW(n) asm volatile("cp.async.wait_group %0;" :: "n"(n) : "memory")

__device__ __forceinline__ void ldsm4(uint32_t r[4], uint32_t a) {
    asm volatile("ldmatrix.sync.aligned.m8n8.x4.shared.b16 {%0,%1,%2,%3}, [%4];"
                 : "=r"(r[0]), "=r"(r[1]), "=r"(r[2]), "=r"(r[3]) : "r"(a));
}
__device__ __forceinline__ void ldsm4t(uint32_t r[4], uint32_t a) {
    asm volatile("ldmatrix.sync.aligned.m8n8.x4.trans.shared.b16 {%0,%1,%2,%3}, [%4];"
                 : "=r"(r[0]), "=r"(r[1]), "=r"(r[2]), "=r"(r[3]) : "r"(a));
}
__device__ __forceinline__ void mma_f16(float c[4], const uint32_t a[4],
                                        uint32_t b0, uint32_t b1) {
    asm volatile("mma.sync.aligned.m16n8k16.row.col.f32.f16.f16.f32 "
                 "{%0,%1,%2,%3}, {%4,%5,%6,%7}, {%8,%9}, {%0,%1,%2,%3};"
                 : "+f"(c[0]), "+f"(c[1]), "+f"(c[2]), "+f"(c[3])
                 : "r"(a[0]), "r"(a[1]), "r"(a[2]), "r"(a[3]), "r"(b0), "r"(b1));
}
__device__ __forceinline__ uint32_t pack2h(fp16 x, fp16 y) {
    __half2 v = __halves2half2(x, y);
    return *reinterpret_cast<uint32_t*>(&v);
}
__device__ __forceinline__ void split_pack(float v0, float v1, uint32_t& hi, uint32_t& lo) {
    fp16 h0 = __float2half_rn(v0), h1 = __float2half_rn(v1);
    fp16 l0 = __float2half_rn(v0 - __half2float(h0));
    fp16 l1 = __float2half_rn(v1 - __half2float(h1));
    hi = pack2h(h0, h1);
    lo = pack2h(l0, l1);
}

// ---------------------------------------------------------------------------
// converts
// ---------------------------------------------------------------------------
__global__ __launch_bounds__(256) void cvt_kernel(
    const float* __restrict__ in, fp16* __restrict__ out, int n4)
{
    const int i = blockIdx.x * blockDim.x + threadIdx.x;
    if (i >= n4) return;
    float4 v = reinterpret_cast<const float4*>(in)[i];
    uint32_t h0 = pack2h(__float2half_rn(v.x), __float2half_rn(v.y));
    uint32_t h1 = pack2h(__float2half_rn(v.z), __float2half_rn(v.w));
    reinterpret_cast<uint2*>(out)[i] = make_uint2(h0, h1);
}

__global__ __launch_bounds__(256) void cvt4_kernel(
    const float* __restrict__ s0, const float* __restrict__ s1,
    const float* __restrict__ s2, const float* __restrict__ s3,
    fp16* __restrict__ dst, int n4)
{
    const int i = blockIdx.x * blockDim.x + threadIdx.x;
    if (i >= n4) return;
    const float* s = (blockIdx.y == 0) ? s0 : (blockIdx.y == 1) ? s1
                   : (blockIdx.y == 2) ? s2 : s3;
    fp16* d = dst + (size_t)blockIdx.y * (size_t)Cv * Cv;
    float4 v = reinterpret_cast<const float4*>(s)[i];
    uint32_t h0 = pack2h(__float2half_rn(v.x), __float2half_rn(v.y));
    uint32_t h1 = pack2h(__float2half_rn(v.z), __float2half_rn(v.w));
    reinterpret_cast<uint2*>(d)[i] = make_uint2(h0, h1);
}

// ---------------------------------------------------------------------------
// mma GEMM (templated): out[M,N] = (Ah[+Al])[M,K] @ Bh[N,K]^T + bias
// CTA 128x128, kblock 64, 8 warps (4x2), warp tile 32x64.
// MODE 2: fused QKV (grid.x covers 3 weight matrices, head-split fp16 out).
// MODE 0: fp32 out (single weight matrix).
// ---------------------------------------------------------------------------
constexpr int GK = 64;                        // k-block
constexpr int GSTR = 72;                      // fp16 row stride (144 B)
constexpr int GT_BYTES = 128 * GSTR * 2;      // 18432
constexpr int NKB = Cv / GK;                  // 16
constexpr int GEMM_SMEM = 6 * GT_BYTES;       // 110592 (both variants)

template <int NTERMS, int MODE>
__global__ __launch_bounds__(256, 2) void mma_gemm(
    const fp16* __restrict__ Ah, const fp16* __restrict__ Al,
    const fp16* __restrict__ Wbase,
    const float* __restrict__ b0, const float* __restrict__ b1,
    const float* __restrict__ b2,
    float* __restrict__ out32,
    fp16* __restrict__ o0, fp16* __restrict__ o1, fp16* __restrict__ o2)
{
    constexpr int STAGE = (NTERMS + 1) * GT_BYTES;
    constexpr int S = (NTERMS == 1) ? 3 : 2;

    extern __shared__ char smem[];
    const uint32_t sbb = smem_u32(smem);
    const int tid = threadIdx.x, lane = tid & 31, wid = tid >> 5;
    const int wm = wid & 3, wn = wid >> 2;
    const int m0 = blockIdx.y * 128;
    const int n0g = blockIdx.x * 128;
    const int wsel = (MODE == 2) ? (n0g >> 10) : 0;
    const int n0 = n0g & 1023;

    const fp16* __restrict__ Bh = Wbase + (size_t)wsel * Cv * Cv;
    const float* __restrict__ bias = (MODE == 2)
        ? ((wsel == 0) ? b0 : (wsel == 1) ? b1 : b2) : b0;
    fp16* __restrict__ oh = (wsel == 0) ? o0 : (wsel == 1) ? o1 : o2;

    auto g2s = [&](int stage, int kb) {
        const uint32_t st = sbb + stage * STAGE;
        const int k0 = kb * GK;
        #pragma unroll
        for (int t = 0; t < NTERMS + 1; t++) {
            const fp16* src = (t == 0) ? Ah : (t == 1 && NTERMS == 2) ? Al : Bh;
            const int row0 = (t == NTERMS) ? n0 : m0;
            const uint32_t tb = st + t * GT_BYTES;
            #pragma unroll
            for (int j = 0; j < 4; j++) {
                const int idx = tid + j * 256;            // 0..1023
                const int r = idx >> 3, c = (idx & 7) * 8;
                CP16(tb + (uint32_t)((r * GSTR + c) * 2),
                     src + (size_t)(row0 + r) * Cv + k0 + c);
            }
        }
    };
    auto fad = [&](uint32_t tb, int rb, int cb) -> uint32_t {
        const int r = rb + (lane & 7) + 8 * ((lane >> 3) & 1);
        const int c = cb + 8 * (lane >> 4);
        return tb + (uint32_t)((r * GSTR + c) * 2);
    };

    float acc[2][8][4] = {};

    #pragma unroll
    for (int s = 0; s < S - 1; s++) { g2s(s, s); CPC(); }

    for (int kb = 0; kb < NKB; kb++) {
        CPW(S - 2);
        __syncthreads();
        if (kb + S - 1 < NKB) g2s((kb + S - 1) % S, kb + S - 1);
        CPC();

        const uint32_t st = sbb + (kb % S) * STAGE;
        #pragma unroll
        for (int ks = 0; ks < 4; ks++) {
            uint32_t ah[2][4], al[2][4], bh4[4][4];
            #pragma unroll
            for (int mt = 0; mt < 2; mt++) {
                ldsm4(ah[mt], fad(st + 0 * GT_BYTES, wm * 32 + mt * 16, ks * 16));
                if (NTERMS == 2)
                    ldsm4(al[mt], fad(st + 1 * GT_BYTES, wm * 32 + mt * 16, ks * 16));
            }
            #pragma unroll
            for (int g = 0; g < 4; g++)
                ldsm4(bh4[g], fad(st + NTERMS * GT_BYTES, wn * 64 + g * 16, ks * 16));
            #pragma unroll
            for (int nt = 0; nt < 8; nt++) {
                const int g = nt >> 1, o = nt & 1;
                const uint32_t bb0 = bh4[g][o], bb1 = bh4[g][o + 2];
                #pragma unroll
                for (int mt = 0; mt < 2; mt++) {
                    mma_f16(acc[mt][nt], ah[mt], bb0, bb1);
                    if (NTERMS == 2)
                        mma_f16(acc[mt][nt], al[mt], bb0, bb1);
                }
            }
        }
    }

    // epilogue
    #pragma unroll
    for (int mt = 0; mt < 2; mt++) {
        const int mr = m0 + wm * 32 + mt * 16 + (lane >> 2);
        #pragma unroll
        for (int half = 0; half < 2; half++) {
            const int m = mr + half * 8;
            const int bb = m >> 11, t = m & (Tv - 1);
            #pragma unroll
            for (int nt = 0; nt < 8; nt++) {
                const int n = n0 + wn * 64 + nt * 8 + (lane & 3) * 2;
                const float v0 = acc[mt][nt][half * 2 + 0] + bias[n];
                const float v1 = acc[mt][nt][half * 2 + 1] + bias[n + 1];
                if (MODE == 0) {
                    *reinterpret_cast<float2*>(out32 + (size_t)m * Cv + n) = make_float2(v0, v1);
                } else {
                    const int h = n >> 6, d = n & 63;
                    const size_t o = (((size_t)(bb * Hn + h)) * Tv + t) * Dv + d;
                    *reinterpret_cast<uint32_t*>(oh + o) =
                        pack2h(__float2half_rn(v0), __float2half_rn(v1));
                }
            }
        }
    }
}

// ---------------------------------------------------------------------------
// mma attention: per (b,h), 128 q rows/CTA, 8 warps, 64-row K/V blocks.
// 4-stage cp.async pipeline; S = Qh Kh^T ; P = exp(S/8) ; O += Ph Vh.
// ---------------------------------------------------------------------------
constexpr int VSTR = 72;                     // fp16 stride (144 B rows)
constexpr int QT_BYTES = 128 * VSTR * 2;     // 18432
constexpr int KT_BYTES = 64 * VSTR * 2;      // 9216
constexpr int ASTAGE = 2 * KT_BYTES;         // Kh, Vh = 18432
constexpr int AS_N = 4;                      // stages
constexpr int ATT_SMEM = QT_BYTES + AS_N * ASTAGE;   // 92160
constexpr int NBLK = Tv / 64;                // 32

__global__ __launch_bounds__(256) void mma_attn()
{
    extern __shared__ char smem[];
    const uint32_t sbb = smem_u32(smem);
    const int tid = threadIdx.x, lane = tid & 31, wid = tid >> 5;
    const int bh = blockIdx.y, q0 = blockIdx.x * 128;

    const fp16* qh = g_qh + (size_t)bh * Tv * Dv;
    const fp16* kh = g_kh + (size_t)bh * Tv * Dv;
    const fp16* vh = g_vh + (size_t)bh * Tv * Dv;

    const uint32_t QH = sbb, ST0 = sbb + QT_BYTES;

    auto g2s = [&](int stage, int blk) {
        const uint32_t st = ST0 + stage * ASTAGE;
        const int s0 = blk * 64;
        #pragma unroll
        for (int j = 0; j < 4; j++) {
            const int idx = tid + j * 256;          // 0..1023
            const int r = (idx >> 3) & 63;
            const int dc = (idx & 7) * 8;
            const uint32_t so = (uint32_t)((r * VSTR + dc) * 2);
            if (idx < 512) CP16(st + so,            kh + (size_t)(s0 + r) * Dv + dc);
            else           CP16(st + KT_BYTES + so, vh + (size_t)(s0 + r) * Dv + dc);
        }
    };
    auto fad = [&](uint32_t tb, int rb, int cb) -> uint32_t {
        const int r = rb + (lane & 7) + 8 * ((lane >> 3) & 1);
        const int c = cb + 8 * (lane >> 4);
        return tb + (uint32_t)((r * VSTR + c) * 2);
    };

    // prologue: group0 = Q + stage0, then stage1, stage2
    #pragma unroll
    for (int j = 0; j < 4; j++) {
        const int idx = tid + j * 256;
        const int r = idx >> 3, dc = (idx & 7) * 8;
        const uint32_t so = (uint32_t)((r * VSTR + dc) * 2);
        CP16(QH + so, qh + (size_t)(q0 + r) * Dv + dc);
    }
    g2s(0, 0); CPC();
    g2s(1, 1); CPC();
    g2s(2, 2); CPC();

    CPW(2); __syncthreads();
    uint32_t qfh[4][4];
    #pragma unroll
    for (int ks = 0; ks < 4; ks++)
        ldsm4(qfh[ks], fad(QH, wid * 16, ks * 16));

    float oacc[8][4] = {};
    float rs0 = 0.f, rs1 = 0.f;

    for (int blk = 0; blk < NBLK; blk++) {
        CPW(2);
        __syncthreads();
        if (blk + 3 < NBLK) g2s((blk + 3) % AS_N, blk + 3);
        CPC();

        const uint32_t st = ST0 + (blk % AS_N) * ASTAGE;

        // S = Qh Kh^T
        float sacc[8][4] = {};
        #pragma unroll
        for (int ks = 0; ks < 4; ks++) {
            uint32_t kf[4][4];
            #pragma unroll
            for (int g = 0; g < 4; g++)
                ldsm4(kf[g], fad(st, g * 16, ks * 16));
            #pragma unroll
            for (int nt = 0; nt < 8; nt++) {
                const int g = nt >> 1, o = nt & 1;
                mma_f16(sacc[nt], qfh[ks], kf[g][o], kf[g][o + 2]);
            }
        }

        // P = exp(S/8)
        uint32_t pah[4][4];
        #pragma unroll
        for (int nt = 0; nt < 8; nt++) {
            const float p0 = __expf(sacc[nt][0] * 0.125f);
            const float p1 = __expf(sacc[nt][1] * 0.125f);
            const float p2 = __expf(sacc[nt][2] * 0.125f);
            const float p3 = __expf(sacc[nt][3] * 0.125f);
            rs0 += p0 + p1;
            rs1 += p2 + p3;
            const int jj = nt >> 1, off = (nt & 1) * 2;
            pah[jj][off]     = pack2h(__float2half_rn(p0), __float2half_rn(p1));
            pah[jj][off + 1] = pack2h(__float2half_rn(p2), __float2half_rn(p3));
        }

        // O += Ph Vh
        #pragma unroll
        for (int ks = 0; ks < 4; ks++) {
            uint32_t vf[4][4];
            #pragma unroll
            for (int g = 0; g < 4; g++)
                ldsm4t(vf[g], fad(st + KT_BYTES, ks * 16, g * 16));
            #pragma unroll
            for (int dt = 0; dt < 8; dt++) {
                const int g = dt >> 1, o = (dt & 1) * 2;
                mma_f16(oacc[dt], pah[ks], vf[g][o], vf[g][o + 1]);
            }
        }
    }

    rs0 += __shfl_xor_sync(0xffffffffu, rs0, 1);
    rs0 += __shfl_xor_sync(0xffffffffu, rs0, 2);
    rs1 += __shfl_xor_sync(0xffffffffu, rs1, 1);
    rs1 += __shfl_xor_sync(0xffffffffu, rs1, 2);
    const float inv0 = 1.0f / rs0, inv1 = 1.0f / rs1;

    const int b = bh >> 4, h = bh & 15;
    const int t0 = q0 + wid * 16 + (lane >> 2);
    #pragma unroll
    for (int dt = 0; dt < 8; dt++) {
        const int col = h * 64 + dt * 8 + (lane & 3) * 2;
        uint32_t hi, lo;
        split_pack(oacc[dt][0] * inv0, oacc[dt][1] * inv0, hi, lo);
        size_t o = (size_t)(b * Tv + t0) * Cv + col;
        *reinterpret_cast<uint32_t*>(g_yh + o) = hi;
        *reinterpret_cast<uint32_t*>(g_yl + o) = lo;
        split_pack(oacc[dt][2] * inv1, oacc[dt][3] * inv1, hi, lo);
        o = (size_t)(b * Tv + t0 + 8) * Cv + col;
        *reinterpret_cast<uint32_t*>(g_yh + o) = hi;
        *reinterpret_cast<uint32_t*>(g_yl + o) = lo;
    }
}

// ---------------------------------------------------------------------------
extern "C" void kernel_launch(void* const* d_in, const int* in_sizes, int n_in,
                              void* d_out, int out_size)
{
    const float* x  = (const float*)d_in[0];
    const float* Wq = (const float*)d_in[1];
    const float* bq = (const float*)d_in[2];
    const float* Wk = (const float*)d_in[3];
    const float* bk = (const float*)d_in[4];
    const float* Wv = (const float*)d_in[5];
    const float* bv = (const float*)d_in[6];
    const float* Wp = (const float*)d_in[7];
    const float* bp = (const float*)d_in[8];
    float* out = (float*)d_out;

    fp16 *xh, *wh, *qh, *kh, *vh, *yh, *yl;
    cudaGetSymbolAddress((void**)&xh, g_xh);
    cudaGetSymbolAddress((void**)&wh, g_wh);
    cudaGetSymbolAddress((void**)&qh, g_qh);
    cudaGetSymbolAddress((void**)&kh, g_kh);
    cudaGetSymbolAddress((void**)&vh, g_vh);
    cudaGetSymbolAddress((void**)&yh, g_yh);
    cudaGetSymbolAddress((void**)&yl, g_yl);

    cudaFuncSetAttribute(mma_gemm<1, 2>, cudaFuncAttributeMaxDynamicSharedMemorySize, GEMM_SMEM);
    cudaFuncSetAttribute(mma_gemm<2, 0>, cudaFuncAttributeMaxDynamicSharedMemorySize, GEMM_SMEM);
    cudaFuncSetAttribute(mma_attn, cudaFuncAttributeMaxDynamicSharedMemorySize, ATT_SMEM);

    const size_t WN = (size_t)Cv * Cv;
    const int xs4 = Mv * Cv / 4, ws4 = (int)(WN / 4);

    cvt_kernel<<<(xs4 + 255) / 256, 256>>>(x, xh, xs4);
    {
        dim3 cg((ws4 + 255) / 256, 4);
        cvt4_kernel<<<cg, 256>>>(Wq, Wk, Wv, Wp, wh, ws4);
    }

    // fused QKV projections: grid.x spans 3 weight matrices
    dim3 qkvGrid(24, Mv / 128);   // (24, 64)
    mma_gemm<1, 2><<<qkvGrid, 256, GEMM_SMEM>>>(
        xh, nullptr, wh, bq, bk, bv, nullptr, qh, kh, vh);

    dim3 aGrid(Tv / 128, Bv * Hn);    // (16, 64)
    mma_attn<<<aGrid, 256, ATT_SMEM>>>();

    // output projection (2-term)
    dim3 pGrid(8, Mv / 128);
    mma_gemm<2, 0><<<pGrid, 256, GEMM_SMEM>>>(
        yh, yl, wh + 3 * WN, bp, bp, bp, out, nullptr, nullptr, nullptr);
}

// round 12
// speedup vs baseline: 14.5993x; 1.0347x over previous
#include <cuda_runtime.h>
#include <cuda_fp16.h>
#include <cstdint>
#include <cstddef>

using fp16 = __half;

constexpr int Bv = 4, Tv = 2048, Cv = 1024, Hn = 16, Dv = 64;
constexpr int Mv = Bv * Tv;   // 8192

// exp(S/8) == exp2(S * 0.125 * log2(e)); scale folded into Q projection.
constexpr float QSCALE = 0.18033688011112042f;   // 0.125 * log2(e)

// ---------------------------------------------------------------------------
// Scratch (device globals)
// ---------------------------------------------------------------------------
__device__ fp16 g_xh[(size_t)Mv * Cv];
__device__ fp16 g_wh[(size_t)4 * Cv * Cv];
__device__ fp16 g_qh[(size_t)Mv * Cv];
__device__ fp16 g_kh[(size_t)Mv * Cv];
__device__ fp16 g_vh[(size_t)Mv * Cv];
__device__ fp16 g_yh[(size_t)Mv * Cv], g_yl[(size_t)Mv * Cv];

// ---------------------------------------------------------------------------
// Helpers
// ---------------------------------------------------------------------------
__device__ __forceinline__ uint32_t smem_u32(const void* p) {
    uint32_t a;
    asm("{ .reg .u64 t; cvta.to.shared.u64 t, %1; cvt.u32.u64 %0, t; }" : "=r"(a) : "l"(p));
    return a;
}
#define CP16(dst, src) \
    asm volatile("cp.async.cg.shared.global [%0], [%1], 16;" \
                 :: "r"(dst), "l"(__cvta_generic_to_global(src)) : "memory")
#define CPC() asm volatile("cp.async.commit_group;" ::: "memory")
#define CPW(n) asm volatile("cp.async.wait_group %0;" :: "n"(n) : "memory")

__device__ __forceinline__ void ldsm4(uint32_t r[4], uint32_t a) {
    asm volatile("ldmatrix.sync.aligned.m8n8.x4.shared.b16 {%0,%1,%2,%3}, [%4];"
                 : "=r"(r[0]), "=r"(r[1]), "=r"(r[2]), "=r"(r[3]) : "r"(a));
}
__device__ __forceinline__ void ldsm4t(uint32_t r[4], uint32_t a) {
    asm volatile("ldmatrix.sync.aligned.m8n8.x4.trans.shared.b16 {%0,%1,%2,%3}, [%4];"
                 : "=r"(r[0]), "=r"(r[1]), "=r"(r[2]), "=r"(r[3]) : "r"(a));
}
__device__ __forceinline__ void mma_f16(float c[4], const uint32_t a[4],
                                        uint32_t b0, uint32_t b1) {
    asm volatile("mma.sync.aligned.m16n8k16.row.col.f32.f16.f16.f32 "
                 "{%0,%1,%2,%3}, {%4,%5,%6,%7}, {%8,%9}, {%0,%1,%2,%3};"
                 : "+f"(c[0]), "+f"(c[1]), "+f"(c[2]), "+f"(c[3])
                 : "r"(a[0]), "r"(a[1]), "r"(a[2]), "r"(a[3]), "r"(b0), "r"(b1));
}
__device__ __forceinline__ uint32_t f22h(float a, float b) {
    __half2 h = __floats2half2_rn(a, b);
    return *reinterpret_cast<uint32_t*>(&h);
}
__device__ __forceinline__ float ex2(float x) {
    float y;
    asm("ex2.approx.f32 %0, %1;" : "=f"(y) : "f"(x));
    return y;
}
__device__ __forceinline__ void split_pack(float v0, float v1, uint32_t& hi, uint32_t& lo) {
    fp16 h0 = __float2half_rn(v0), h1 = __float2half_rn(v1);
    fp16 l0 = __float2half_rn(v0 - __half2float(h0));
    fp16 l1 = __float2half_rn(v1 - __half2float(h1));
    hi = f22h(__half2float(h0), __half2float(h1));
    lo = f22h(__half2float(l0), __half2float(l1));
}

// ---------------------------------------------------------------------------
// converts
// ---------------------------------------------------------------------------
__global__ __launch_bounds__(256) void cvt_kernel(
    const float* __restrict__ in, fp16* __restrict__ out, int n4)
{
    const int i = blockIdx.x * blockDim.x + threadIdx.x;
    if (i >= n4) return;
    float4 v = reinterpret_cast<const float4*>(in)[i];
    reinterpret_cast<uint2*>(out)[i] = make_uint2(f22h(v.x, v.y), f22h(v.z, v.w));
}

__global__ __launch_bounds__(256) void cvt4_kernel(
    const float* __restrict__ s0, const float* __restrict__ s1,
    const float* __restrict__ s2, const float* __restrict__ s3,
    fp16* __restrict__ dst, int n4)
{
    const int i = blockIdx.x * blockDim.x + threadIdx.x;
    if (i >= n4) return;
    const float* s = (blockIdx.y == 0) ? s0 : (blockIdx.y == 1) ? s1
                   : (blockIdx.y == 2) ? s2 : s3;
    fp16* d = dst + (size_t)blockIdx.y * (size_t)Cv * Cv;
    float4 v = reinterpret_cast<const float4*>(s)[i];
    reinterpret_cast<uint2*>(d)[i] = make_uint2(f22h(v.x, v.y), f22h(v.z, v.w));
}

// ---------------------------------------------------------------------------
// mma GEMM (templated): out[M,N] = (Ah[+Al])[M,K] @ Bh[N,K]^T + bias
// CTA 128x128, kblock 64, 8 warps (4x2), warp tile 32x64.
// MODE 2: fused QKV (grid.x covers 3 weight matrices; wsel==0 output scaled
//         by QSCALE to fold the softmax scale into Q). MODE 0: fp32 out.
// ---------------------------------------------------------------------------
constexpr int GK = 64;
constexpr int GSTR = 72;                      // fp16 row stride (144 B)
constexpr int GT_BYTES = 128 * GSTR * 2;      // 18432
constexpr int NKB = Cv / GK;                  // 16
constexpr int GEMM_SMEM = 6 * GT_BYTES;       // 110592

template <int NTERMS, int MODE>
__global__ __launch_bounds__(256, 2) void mma_gemm(
    const fp16* __restrict__ Ah, const fp16* __restrict__ Al,
    const fp16* __restrict__ Wbase,
    const float* __restrict__ b0, const float* __restrict__ b1,
    const float* __restrict__ b2,
    float* __restrict__ out32,
    fp16* __restrict__ o0, fp16* __restrict__ o1, fp16* __restrict__ o2)
{
    constexpr int STAGE = (NTERMS + 1) * GT_BYTES;
    constexpr int S = (NTERMS == 1) ? 3 : 2;

    extern __shared__ char smem[];
    const uint32_t sbb = smem_u32(smem);
    const int tid = threadIdx.x, lane = tid & 31, wid = tid >> 5;
    const int wm = wid & 3, wn = wid >> 2;
    const int m0 = blockIdx.y * 128;
    const int n0g = blockIdx.x * 128;
    const int wsel = (MODE == 2) ? (n0g >> 10) : 0;
    const int n0 = n0g & 1023;

    const fp16* __restrict__ Bh = Wbase + (size_t)wsel * Cv * Cv;
    const float* __restrict__ bias = (MODE == 2)
        ? ((wsel == 0) ? b0 : (wsel == 1) ? b1 : b2) : b0;
    fp16* __restrict__ oh = (wsel == 0) ? o0 : (wsel == 1) ? o1 : o2;

    auto g2s = [&](int stage, int kb) {
        const uint32_t st = sbb + stage * STAGE;
        const int k0 = kb * GK;
        #pragma unroll
        for (int t = 0; t < NTERMS + 1; t++) {
            const fp16* src = (t == 0) ? Ah : (t == 1 && NTERMS == 2) ? Al : Bh;
            const int row0 = (t == NTERMS) ? n0 : m0;
            const uint32_t tb = st + t * GT_BYTES;
            #pragma unroll
            for (int j = 0; j < 4; j++) {
                const int idx = tid + j * 256;
                const int r = idx >> 3, c = (idx & 7) * 8;
                CP16(tb + (uint32_t)((r * GSTR + c) * 2),
                     src + (size_t)(row0 + r) * Cv + k0 + c);
            }
        }
    };
    auto fad = [&](uint32_t tb, int rb, int cb) -> uint32_t {
        const int r = rb + (lane & 7) + 8 * ((lane >> 3) & 1);
        const int c = cb + 8 * (lane >> 4);
        return tb + (uint32_t)((r * GSTR + c) * 2);
    };

    float acc[2][8][4] = {};

    #pragma unroll
    for (int s = 0; s < S - 1; s++) { g2s(s, s); CPC(); }

    for (int kb = 0; kb < NKB; kb++) {
        CPW(S - 2);
        __syncthreads();
        if (kb + S - 1 < NKB) g2s((kb + S - 1) % S, kb + S - 1);
        CPC();

        const uint32_t st = sbb + (kb % S) * STAGE;
        #pragma unroll
        for (int ks = 0; ks < 4; ks++) {
            uint32_t ah[2][4], al[2][4], bh4[4][4];
            #pragma unroll
            for (int mt = 0; mt < 2; mt++) {
                ldsm4(ah[mt], fad(st + 0 * GT_BYTES, wm * 32 + mt * 16, ks * 16));
                if (NTERMS == 2)
                    ldsm4(al[mt], fad(st + 1 * GT_BYTES, wm * 32 + mt * 16, ks * 16));
            }
            #pragma unroll
            for (int g = 0; g < 4; g++)
                ldsm4(bh4[g], fad(st + NTERMS * GT_BYTES, wn * 64 + g * 16, ks * 16));
            #pragma unroll
            for (int nt = 0; nt < 8; nt++) {
                const int g = nt >> 1, o = nt & 1;
                const uint32_t bb0 = bh4[g][o], bb1 = bh4[g][o + 2];
                #pragma unroll
                for (int mt = 0; mt < 2; mt++) {
                    mma_f16(acc[mt][nt], ah[mt], bb0, bb1);
                    if (NTERMS == 2)
                        mma_f16(acc[mt][nt], al[mt], bb0, bb1);
                }
            }
        }
    }

    // epilogue
    const float osc = (MODE == 2 && wsel == 0) ? QSCALE : 1.0f;
    #pragma unroll
    for (int mt = 0; mt < 2; mt++) {
        const int mr = m0 + wm * 32 + mt * 16 + (lane >> 2);
        #pragma unroll
        for (int half = 0; half < 2; half++) {
            const int m = mr + half * 8;
            const int bb = m >> 11, t = m & (Tv - 1);
            #pragma unroll
            for (int nt = 0; nt < 8; nt++) {
                const int n = n0 + wn * 64 + nt * 8 + (lane & 3) * 2;
                const float v0 = (acc[mt][nt][half * 2 + 0] + bias[n]) * osc;
                const float v1 = (acc[mt][nt][half * 2 + 1] + bias[n + 1]) * osc;
                if (MODE == 0) {
                    *reinterpret_cast<float2*>(out32 + (size_t)m * Cv + n) = make_float2(v0, v1);
                } else {
                    const int h = n >> 6, d = n & 63;
                    const size_t o = (((size_t)(bb * Hn + h)) * Tv + t) * Dv + d;
                    *reinterpret_cast<uint32_t*>(oh + o) = f22h(v0, v1);
                }
            }
        }
    }
}

// ---------------------------------------------------------------------------
// mma attention: per (b,h), 128 q rows/CTA, 8 warps, 128-row K/V stages
// (2 sub-chunks of 64), 2-stage pipeline, one barrier per stage.
// S = Qs Kh^T (Q pre-scaled) ; P = ex2(S) ; O += Ph Vh ; deferred divide.
// ---------------------------------------------------------------------------
constexpr int VSTR = 72;                     // fp16 stride (144 B rows)
constexpr int QT_BYTES = 128 * VSTR * 2;     // 18432
constexpr int KT2 = 128 * VSTR * 2;          // 18432 (K half of stage)
constexpr int ASTG = 2 * KT2;                // 36864 (K + V, 128 rows each)
constexpr int ATT_SMEM = QT_BYTES + 2 * ASTG;   // 92160
constexpr int NBLK = Tv / 128;               // 16

__global__ __launch_bounds__(256, 2) void mma_attn()
{
    extern __shared__ char smem[];
    const uint32_t sbb = smem_u32(smem);
    const int tid = threadIdx.x, lane = tid & 31, wid = tid >> 5;
    const int bh = blockIdx.y, q0 = blockIdx.x * 128;

    const fp16* qh = g_qh + (size_t)bh * Tv * Dv;
    const fp16* kh = g_kh + (size_t)bh * Tv * Dv;
    const fp16* vh = g_vh + (size_t)bh * Tv * Dv;

    const uint32_t QH = sbb, ST0 = sbb + QT_BYTES;

    auto g2s = [&](int stage, int blk) {
        const uint32_t st = ST0 + stage * ASTG;
        const int s0 = blk * 128;
        #pragma unroll
        for (int j = 0; j < 8; j++) {
            const int idx = tid + j * 256;          // 0..2047
            const int r = (idx >> 3) & 127;
            const int dc = (idx & 7) * 8;
            const uint32_t so = (uint32_t)((r * VSTR + dc) * 2);
            if (idx < 1024) CP16(st + so,       kh + (size_t)(s0 + r) * Dv + dc);
            else            CP16(st + KT2 + so, vh + (size_t)(s0 + r) * Dv + dc);
        }
    };
    auto fad = [&](uint32_t tb, int rb, int cb) -> uint32_t {
        const int r = rb + (lane & 7) + 8 * ((lane >> 3) & 1);
        const int c = cb + 8 * (lane >> 4);
        return tb + (uint32_t)((r * VSTR + c) * 2);
    };

    // prologue: Q + stage0 in one group
    #pragma unroll
    for (int j = 0; j < 4; j++) {
        const int idx = tid + j * 256;
        const int r = idx >> 3, dc = (idx & 7) * 8;
        CP16(QH + (uint32_t)((r * VSTR + dc) * 2), qh + (size_t)(q0 + r) * Dv + dc);
    }
    g2s(0, 0); CPC();

    CPW(0); __syncthreads();
    uint32_t qfh[4][4];
    #pragma unroll
    for (int ks = 0; ks < 4; ks++)
        ldsm4(qfh[ks], fad(QH, wid * 16, ks * 16));

    float oacc[8][4] = {};
    float rs0 = 0.f, rs1 = 0.f;

    for (int blk = 0; blk < NBLK; blk++) {
        CPW(0);
        __syncthreads();   // loads visible AND prior compute on this stage done
        if (blk + 1 < NBLK) g2s((blk + 1) & 1, blk + 1);
        CPC();

        const uint32_t st = ST0 + (blk & 1) * ASTG;

        #pragma unroll
        for (int c = 0; c < 2; c++) {            // two 64-row sub-chunks
            const uint32_t kb = st + (uint32_t)(c * 64 * VSTR * 2);
            const uint32_t vb = st + KT2 + (uint32_t)(c * 64 * VSTR * 2);

            // S = Qs Kh^T (Q carries the softmax scale)
            float sacc[8][4] = {};
            #pragma unroll
            for (int ks = 0; ks < 4; ks++) {
                uint32_t kf[4][4];
                #pragma unroll
                for (int g = 0; g < 4; g++)
                    ldsm4(kf[g], fad(kb, g * 16, ks * 16));
                #pragma unroll
                for (int nt = 0; nt < 8; nt++) {
                    const int g = nt >> 1, o = nt & 1;
                    mma_f16(sacc[nt], qfh[ks], kf[g][o], kf[g][o + 2]);
                }
            }

            // P = ex2(S)
            uint32_t pah[4][4];
            #pragma unroll
            for (int nt = 0; nt < 8; nt++) {
                const float p0 = ex2(sacc[nt][0]);
                const float p1 = ex2(sacc[nt][1]);
                const float p2 = ex2(sacc[nt][2]);
                const float p3 = ex2(sacc[nt][3]);
                rs0 += p0 + p1;
                rs1 += p2 + p3;
                const int jj = nt >> 1, off = (nt & 1) * 2;
                pah[jj][off]     = f22h(p0, p1);
                pah[jj][off + 1] = f22h(p2, p3);
            }

            // O += Ph Vh
            #pragma unroll
            for (int ks = 0; ks < 4; ks++) {
                uint32_t vf[4][4];
                #pragma unroll
                for (int g = 0; g < 4; g++)
                    ldsm4t(vf[g], fad(vb, ks * 16, g * 16));
                #pragma unroll
                for (int dt = 0; dt < 8; dt++) {
                    const int g = dt >> 1, o = (dt & 1) * 2;
                    mma_f16(oacc[dt], pah[ks], vf[g][o], vf[g][o + 1]);
                }
            }
        }
    }

    rs0 += __shfl_xor_sync(0xffffffffu, rs0, 1);
    rs0 += __shfl_xor_sync(0xffffffffu, rs0, 2);
    rs1 += __shfl_xor_sync(0xffffffffu, rs1, 1);
    rs1 += __shfl_xor_sync(0xffffffffu, rs1, 2);
    const float inv0 = 1.0f / rs0, inv1 = 1.0f / rs1;

    const int b = bh >> 4, h = bh & 15;
    const int t0 = q0 + wid * 16 + (lane >> 2);
    #pragma unroll
    for (int dt = 0; dt < 8; dt++) {
        const int col = h * 64 + dt * 8 + (lane & 3) * 2;
        uint32_t hi, lo;
        split_pack(oacc[dt][0] * inv0, oacc[dt][1] * inv0, hi, lo);
        size_t o = (size_t)(b * Tv + t0) * Cv + col;
        *reinterpret_cast<uint32_t*>(g_yh + o) = hi;
        *reinterpret_cast<uint32_t*>(g_yl + o) = lo;
        split_pack(oacc[dt][2] * inv1, oacc[dt][3] * inv1, hi, lo);
        o = (size_t)(b * Tv + t0 + 8) * Cv + col;
        *reinterpret_cast<uint32_t*>(g_yh + o) = hi;
        *reinterpret_cast<uint32_t*>(g_yl + o) = lo;
    }
}

// ---------------------------------------------------------------------------
extern "C" void kernel_launch(void* const* d_in, const int* in_sizes, int n_in,
                              void* d_out, int out_size)
{
    const float* x  = (const float*)d_in[0];
    const float* Wq = (const float*)d_in[1];
    const float* bq = (const float*)d_in[2];
    const float* Wk = (const float*)d_in[3];
    const float* bk = (const float*)d_in[4];
    const float* Wv = (const float*)d_in[5];
    const float* bv = (const float*)d_in[6];
    const float* Wp = (const float*)d_in[7];
    const float* bp = (const float*)d_in[8];
    float* out = (float*)d_out;

    fp16 *xh, *wh, *qh, *kh, *vh, *yh, *yl;
    cudaGetSymbolAddress((void**)&xh, g_xh);
    cudaGetSymbolAddress((void**)&wh, g_wh);
    cudaGetSymbolAddress((void**)&qh, g_qh);
    cudaGetSymbolAddress((void**)&kh, g_kh);
    cudaGetSymbolAddress((void**)&vh, g_vh);
    cudaGetSymbolAddress((void**)&yh, g_yh);
    cudaGetSymbolAddress((void**)&yl, g_yl);

    cudaFuncSetAttribute(mma_gemm<1, 2>, cudaFuncAttributeMaxDynamicSharedMemorySize, GEMM_SMEM);
    cudaFuncSetAttribute(mma_gemm<2, 0>, cudaFuncAttributeMaxDynamicSharedMemorySize, GEMM_SMEM);
    cudaFuncSetAttribute(mma_attn, cudaFuncAttributeMaxDynamicSharedMemorySize, ATT_SMEM);

    const size_t WN = (size_t)Cv * Cv;
    const int xs4 = Mv * Cv / 4, ws4 = (int)(WN / 4);

    cvt_kernel<<<(xs4 + 255) / 256, 256>>>(x, xh, xs4);
    {
        dim3 cg((ws4 + 255) / 256, 4);
        cvt4_kernel<<<cg, 256>>>(Wq, Wk, Wv, Wp, wh, ws4);
    }

    dim3 qkvGrid(24, Mv / 128);
    mma_gemm<1, 2><<<qkvGrid, 256, GEMM_SMEM>>>(
        xh, nullptr, wh, bq, bk, bv, nullptr, qh, kh, vh);

    dim3 aGrid(Tv / 128, Bv * Hn);
    mma_attn<<<aGrid, 256, ATT_SMEM>>>();

    dim3 pGrid(8, Mv / 128);
    mma_gemm<2, 0><<<pGrid, 256, GEMM_SMEM>>>(
        yh, yl, wh + 3 * WN, bp, bp, bp, out, nullptr, nullptr, nullptr);
}